// round 7
// baseline (speedup 1.0000x reference)
#include <cuda_runtime.h>
#include <cuda_bf16.h>
#include <cstdint>
#include <math.h>

// Problem constants
#define B_      4
#define S_      4096
#define H_      1280
#define C_      2048
#define T_      77
#define I_      32
#define NHEADS  20
#define DH      64
#define L_      (T_ + I_)       // 109
#define ROWS    (B_ * S_)       // 16384

// ---------------------------------------------------------------------------
// Scratch (device globals; no allocations allowed)
// ---------------------------------------------------------------------------
__device__ float         g_q[ROWS * H_];        // q projection (fp32, read by attn)
__device__ __nv_bfloat16 g_att_hi[ROWS * H_];   // attention out, bf16 split
__device__ __nv_bfloat16 g_att_lo[ROWS * H_];
__device__ __nv_bfloat16 g_hs_hi[ROWS * H_];    // hidden_states, bf16 split
__device__ __nv_bfloat16 g_hs_lo[ROWS * H_];
__device__ __nv_bfloat16 g_wq_hi[H_ * H_];      // Wq^T [N,K], bf16 split
__device__ __nv_bfloat16 g_wq_lo[H_ * H_];
__device__ __nv_bfloat16 g_wo_hi[H_ * H_];      // Wout^T [N,K], bf16 split
__device__ __nv_bfloat16 g_wo_lo[H_ * H_];
__device__ float         g_k[B_ * L_ * H_];
__device__ float         g_v[B_ * L_ * H_];

// ---------------------------------------------------------------------------
// PTX helpers (sm_100 base target — NO tcgen05, which needs the 'a' variant)
// ---------------------------------------------------------------------------
#define CP_ASYNC_16(dst, src) \
    asm volatile("cp.async.cg.shared.global [%0], [%1], 16;" :: "r"(dst), "l"(src) : "memory")
#define CP_COMMIT() asm volatile("cp.async.commit_group;" ::: "memory")
#define CP_WAIT1()  asm volatile("cp.async.wait_group 1;" ::: "memory")

__device__ __forceinline__ uint32_t smem_to_u32(const void* p) {
    uint32_t a;
    asm("{ .reg .u64 t; cvta.to.shared.u64 t, %1; cvt.u32.u64 %0, t; }"
        : "=r"(a) : "l"(p));
    return a;
}

__device__ __forceinline__ void ldsm_x4(uint32_t& r0, uint32_t& r1,
                                        uint32_t& r2, uint32_t& r3, uint32_t addr) {
    asm volatile("ldmatrix.sync.aligned.m8n8.x4.shared.b16 {%0,%1,%2,%3}, [%4];"
                 : "=r"(r0), "=r"(r1), "=r"(r2), "=r"(r3) : "r"(addr));
}

__device__ __forceinline__ void mma_bf16(float* d, const uint32_t* a,
                                         uint32_t b0, uint32_t b1) {
    asm volatile(
        "mma.sync.aligned.m16n8k16.row.col.f32.bf16.bf16.f32 "
        "{%0,%1,%2,%3}, {%4,%5,%6,%7}, {%8,%9}, {%0,%1,%2,%3};"
        : "+f"(d[0]), "+f"(d[1]), "+f"(d[2]), "+f"(d[3])
        : "r"(a[0]), "r"(a[1]), "r"(a[2]), "r"(a[3]), "r"(b0), "r"(b1));
}

// Packed f32x2 ops (Blackwell, base sm_100 target)
__device__ __forceinline__ uint64_t fma2(uint64_t a, uint64_t b, uint64_t c) {
    uint64_t d;
    asm("fma.rn.f32x2 %0, %1, %2, %3;" : "=l"(d) : "l"(a), "l"(b), "l"(c));
    return d;
}
__device__ __forceinline__ uint64_t add2(uint64_t a, uint64_t b) {
    uint64_t d;
    asm("add.rn.f32x2 %0, %1, %2;" : "=l"(d) : "l"(a), "l"(b));
    return d;
}
__device__ __forceinline__ uint64_t mul2(uint64_t a, uint64_t b) {
    uint64_t d;
    asm("mul.rn.f32x2 %0, %1, %2;" : "=l"(d) : "l"(a), "l"(b));
    return d;
}
__device__ __forceinline__ uint64_t pack2(float x) {
    uint64_t d;
    uint32_t u = __float_as_uint(x);
    asm("mov.b64 %0, {%1, %1};" : "=l"(d) : "r"(u));
    return d;
}
__device__ __forceinline__ float hsum2(uint64_t v) {
    uint32_t lo, hi;
    asm("mov.b64 {%0, %1}, %2;" : "=r"(lo), "=r"(hi) : "l"(v));
    return __uint_as_float(lo) + __uint_as_float(hi);
}

// bf16 two-term split of fp32
__device__ __forceinline__ void bf16split(float x, __nv_bfloat16& h, __nv_bfloat16& l) {
    h = __float2bfloat16_rn(x);
    l = __float2bfloat16_rn(x - __bfloat162float(h));
}

// ---------------------------------------------------------------------------
// Prep 1: elementwise split of hidden_states -> g_hs_hi/lo
// ---------------------------------------------------------------------------
__global__ void __launch_bounds__(256) split_kernel(const float* __restrict__ src)
{
    size_t i = ((size_t)blockIdx.x * 256 + threadIdx.x) * 4;
    float4 v = *(const float4*)(src + i);
    __nv_bfloat16 h0, l0, h1, l1, h2, l2, h3, l3;
    bf16split(v.x, h0, l0); bf16split(v.y, h1, l1);
    bf16split(v.z, h2, l2); bf16split(v.w, h3, l3);
    *(__nv_bfloat162*)(g_hs_hi + i)     = __nv_bfloat162(h0, h1);
    *(__nv_bfloat162*)(g_hs_hi + i + 2) = __nv_bfloat162(h2, h3);
    *(__nv_bfloat162*)(g_hs_lo + i)     = __nv_bfloat162(l0, l1);
    *(__nv_bfloat162*)(g_hs_lo + i + 2) = __nv_bfloat162(l2, l3);
}

// ---------------------------------------------------------------------------
// Prep 2: transpose+split Wq and Wout -> [N, K] bf16 splits
// ---------------------------------------------------------------------------
__global__ void __launch_bounds__(256) tsplit_kernel(const float* __restrict__ Wq,
                                                     const float* __restrict__ Wout)
{
    __shared__ float t[32][33];
    const float* W = blockIdx.z ? Wout : Wq;
    __nv_bfloat16* dh = blockIdx.z ? g_wo_hi : g_wq_hi;
    __nv_bfloat16* dl = blockIdx.z ? g_wo_lo : g_wq_lo;
    int bx = blockIdx.x * 32, by = blockIdx.y * 32;
    int tx = threadIdx.x, ty = threadIdx.y;
    #pragma unroll
    for (int i = 0; i < 4; i++)
        t[ty + 8 * i][tx] = W[(size_t)(by + ty + 8 * i) * H_ + bx + tx];
    __syncthreads();
    #pragma unroll
    for (int i = 0; i < 4; i++) {
        float v = t[tx][ty + 8 * i];
        __nv_bfloat16 h, l;
        bf16split(v, h, l);
        size_t o = (size_t)(bx + ty + 8 * i) * H_ + by + tx;   // [n][k]
        dh[o] = h;
        dl[o] = l;
    }
}

// ---------------------------------------------------------------------------
// KV build: fp32 SIMT, small (436x1280x2048 effective)
// ---------------------------------------------------------------------------
__global__ void __launch_bounds__(256) kv_kernel(
    const float* __restrict__ ehs, const float* __restrict__ idemb,
    const float* __restrict__ Wk, const float* __restrict__ Wv,
    const float* __restrict__ Wid_k, const float* __restrict__ Wid_v)
{
    const int z = blockIdx.z;
    const bool is_id = (z >= 2);
    const bool is_v  = (z & 1);
    const float* A = is_id ? idemb : ehs;
    const float* W = is_id ? (is_v ? Wid_v : Wid_k) : (is_v ? Wv : Wk);
    float* outp = is_v ? g_v : g_k;
    const int Mloc = is_id ? (2 * I_) : (B_ * T_);

    const int m0 = blockIdx.y * 64;
    if (m0 >= Mloc) return;
    const int n0 = blockIdx.x * 64;

    __shared__ float As[16][68];
    __shared__ float Bs[16][64];

    const int tid  = threadIdx.x;
    const int arow = tid >> 2;
    const int ac4  = (tid & 3) * 4;
    const int brow = tid >> 4;
    const int bc4  = (tid & 15) * 4;
    const int tx   = tid & 15;
    const int ty   = tid >> 4;

    float acc[4][4];
    #pragma unroll
    for (int i = 0; i < 4; i++)
        #pragma unroll
        for (int j = 0; j < 4; j++) acc[i][j] = 0.f;

    for (int k0 = 0; k0 < C_; k0 += 16) {
        float4 av = make_float4(0.f, 0.f, 0.f, 0.f);
        if (m0 + arow < Mloc)
            av = *(const float4*)(A + (size_t)(m0 + arow) * C_ + k0 + ac4);
        float4 bv = *(const float4*)(W + (size_t)(k0 + brow) * H_ + n0 + bc4);
        __syncthreads();
        As[ac4 + 0][arow] = av.x;
        As[ac4 + 1][arow] = av.y;
        As[ac4 + 2][arow] = av.z;
        As[ac4 + 3][arow] = av.w;
        *(float4*)&Bs[brow][bc4] = bv;
        __syncthreads();
        #pragma unroll
        for (int kk = 0; kk < 16; kk++) {
            float4 a = *(const float4*)&As[kk][ty * 4];
            float4 b = *(const float4*)&Bs[kk][tx * 4];
            float am[4] = {a.x, a.y, a.z, a.w};
            float bn[4] = {b.x, b.y, b.z, b.w};
            #pragma unroll
            for (int i = 0; i < 4; i++)
                #pragma unroll
                for (int j = 0; j < 4; j++)
                    acc[i][j] += am[i] * bn[j];
        }
    }

    #pragma unroll
    for (int i = 0; i < 4; i++) {
        int r = m0 + ty * 4 + i;
        if (r >= Mloc) continue;
        float4 o = make_float4(acc[i][0], acc[i][1], acc[i][2], acc[i][3]);
        if (!is_id) {
            int batch = r / T_, pos = r % T_;
            *(float4*)(outp + (size_t)(batch * L_ + pos) * H_ + n0 + tx * 4) = o;
        } else {
            int hb = r >> 5, ii = r & 31;
            *(float4*)(outp + (size_t)( hb      * L_ + T_ + ii) * H_ + n0 + tx * 4) = o;
            *(float4*)(outp + (size_t)((hb + 2) * L_ + T_ + ii) * H_ + n0 + tx * 4) = o;
        }
    }
}

// ---------------------------------------------------------------------------
// HMMA bf16x3 GEMM: C[M,1280] = A[M,1280] @ B^T (B stored [N,K] splits).
// CTA tile 64x128 (R7: was 128x128), 8 warps (4x2), warp tile 16x64,
// 3 CTAs/SM (reg cap 85). 2560 CTAs / 444 concurrent = 5.77 waves -> 4%
// quantization loss (was 14% at 4.32/5). 3-stage cp.async, 1 barrier/iter.
// Smem tiles 64B rows, XOR swizzle — conflict-free ldmatrix & cp.async.
// ---------------------------------------------------------------------------
#define GK       H_          // 1280
#define GN       H_          // 1280
#define BK       32
#define NIT      (GK / BK)   // 40
#define TM       64          // CTA M tile
#define TILE_A   (TM * 64)   // 4096 B
#define TILE_Bb  (128 * 64)  // 8192 B
#define STAGE_B  (2 * TILE_A + 2 * TILE_Bb)  // 24576 B
#define NSTAGE   3

__device__ __forceinline__ uint32_t swz(int row, int chunk) {
    return (uint32_t)(row * 64 + ((chunk ^ ((row >> 1) & 3)) << 4));
}

// A tile: 64 rows x 32 bf16 = 256 x 16B chunks; 1 chunk per thread
__device__ __forceinline__ void fill_a(uint32_t dst, const __nv_bfloat16* src,
                                       int k0, int tid)
{
    int row = tid >> 2;
    int c   = tid & 3;
    CP_ASYNC_16(dst + swz(row, c), src + (size_t)row * GK + k0 + c * 8);
}

// B tile: 128 rows x 32 bf16 = 512 chunks; 2 per thread
__device__ __forceinline__ void fill_b(uint32_t dst, const __nv_bfloat16* src,
                                       int k0, int tid)
{
    #pragma unroll
    for (int i = 0; i < 2; i++) {
        int idx = i * 256 + tid;
        int row = idx >> 2;
        int c   = idx & 3;
        CP_ASYNC_16(dst + swz(row, c), src + (size_t)row * GK + k0 + c * 8);
    }
}

template<int MODE>
__global__ void __launch_bounds__(256, 3) gemm_hmma(
    const float* __restrict__ bias, float* __restrict__ Cp)
{
    const __nv_bfloat16* Ahi = (MODE == 0) ? g_hs_hi : g_att_hi;
    const __nv_bfloat16* Alo = (MODE == 0) ? g_hs_lo : g_att_lo;
    const __nv_bfloat16* Bhi = (MODE == 0) ? g_wq_hi : g_wo_hi;
    const __nv_bfloat16* Blo = (MODE == 0) ? g_wq_lo : g_wo_lo;
    float* C = (MODE == 0) ? (float*)g_q : Cp;

    extern __shared__ char smem[];
    const uint32_t sb = smem_to_u32(smem);

    const int tid  = threadIdx.x;
    const int wid  = tid >> 5;
    const int lane = tid & 31;
    const int wm   = wid >> 1;          // 0..3 (16-row M blocks)
    const int wn   = wid & 1;           // 0..1 (64-col N blocks)
    const int n0 = blockIdx.x * 128;
    const int m0 = blockIdx.y * TM;

    const __nv_bfloat16* aH = Ahi + (size_t)m0 * GK;
    const __nv_bfloat16* aL = Alo + (size_t)m0 * GK;
    const __nv_bfloat16* bH = Bhi + (size_t)n0 * GK;
    const __nv_bfloat16* bL = Blo + (size_t)n0 * GK;

    const int a_row_off = (lane & 7) + ((lane >> 3) & 1) * 8;
    const int a_half    = lane >> 4;
    const int b_row_off = (lane & 7) + ((lane >> 4) & 1) * 8;
    const int b_half    = (lane >> 3) & 1;

    float acc[8][4];
    #pragma unroll
    for (int nt = 0; nt < 8; nt++)
        #pragma unroll
        for (int c = 0; c < 4; c++) acc[nt][c] = 0.f;

    // Prologue: fill stages 0 and 1
    #pragma unroll
    for (int st = 0; st < 2; st++) {
        uint32_t s = sb + st * STAGE_B;
        fill_a(s,                        aH, st * BK, tid);
        fill_a(s + TILE_A,               aL, st * BK, tid);
        fill_b(s + 2 * TILE_A,           bH, st * BK, tid);
        fill_b(s + 2 * TILE_A + TILE_Bb, bL, st * BK, tid);
        CP_COMMIT();
    }

    int stage = 0;
    for (int it = 0; it < NIT; it++) {
        uint32_t s = sb + stage * STAGE_B;
        CP_WAIT1();
        __syncthreads();

        const uint32_t sAh = s;
        const uint32_t sAl = s + TILE_A;
        const uint32_t sBh = s + 2 * TILE_A;
        const uint32_t sBl = s + 2 * TILE_A + TILE_Bb;

        #pragma unroll
        for (int ks = 0; ks < 2; ks++) {
            uint32_t fAh[4], fAl[4];
            {
                int row = wm * 16 + a_row_off;
                uint32_t ad = swz(row, ks * 2 + a_half);
                ldsm_x4(fAh[0], fAh[1], fAh[2], fAh[3], sAh + ad);
                ldsm_x4(fAl[0], fAl[1], fAl[2], fAl[3], sAl + ad);
            }
            #pragma unroll
            for (int g = 0; g < 4; g++) {
                int row = wn * 64 + g * 16 + b_row_off;
                uint32_t bd = swz(row, ks * 2 + b_half);
                uint32_t b0, b1, b2, b3;
                ldsm_x4(b0, b1, b2, b3, sBh + bd);
                mma_bf16(acc[g * 2 + 0], fAh, b0, b1);
                mma_bf16(acc[g * 2 + 1], fAh, b2, b3);
                mma_bf16(acc[g * 2 + 0], fAl, b0, b1);
                mma_bf16(acc[g * 2 + 1], fAl, b2, b3);
            }
            #pragma unroll
            for (int g = 0; g < 4; g++) {
                int row = wn * 64 + g * 16 + b_row_off;
                uint32_t bd = swz(row, ks * 2 + b_half);
                uint32_t b0, b1, b2, b3;
                ldsm_x4(b0, b1, b2, b3, sBl + bd);
                mma_bf16(acc[g * 2 + 0], fAh, b0, b1);
                mma_bf16(acc[g * 2 + 1], fAh, b2, b3);
            }
        }

        if (it + 2 < NIT) {
            int fs = stage + 2 >= NSTAGE ? stage + 2 - NSTAGE : stage + 2;
            uint32_t f = sb + fs * STAGE_B;
            int k0 = (it + 2) * BK;
            fill_a(f,                        aH, k0, tid);
            fill_a(f + TILE_A,               aL, k0, tid);
            fill_b(f + 2 * TILE_A,           bH, k0, tid);
            fill_b(f + 2 * TILE_A + TILE_Bb, bL, k0, tid);
        }
        CP_COMMIT();
        stage = stage + 1 >= NSTAGE ? 0 : stage + 1;
    }

    // Epilogue
    const int gid = lane >> 2, tig = lane & 3;
    #pragma unroll
    for (int nt = 0; nt < 8; nt++) {
        int r   = m0 + wm * 16 + gid;
        int col = n0 + wn * 64 + nt * 8 + tig * 2;
        float b0v = 0.f, b1v = 0.f;
        if (MODE == 1) { b0v = bias[col]; b1v = bias[col + 1]; }
        float2 v0 = make_float2(acc[nt][0] + b0v, acc[nt][1] + b1v);
        float2 v1 = make_float2(acc[nt][2] + b0v, acc[nt][3] + b1v);
        *(float2*)(C + (size_t)r * GN + col)       = v0;
        *(float2*)(C + (size_t)(r + 8) * GN + col) = v1;
    }
}

// ---------------------------------------------------------------------------
// Attention, packed f32x2. 128-thread CTAs (R7): ~150 live regs/thread made
// 256-thread CTAs 1 CTA/SM reg-limited; 128 threads -> 3 CTAs/SM (12 warps).
// ---------------------------------------------------------------------------
__global__ void __launch_bounds__(128) attn_kernel()
{
    extern __shared__ float asmem[];
    float* Ks = asmem;
    float* Vs = asmem + L_ * DH;

    const int tid = threadIdx.x;
    const int bh = blockIdx.y;
    const int batch = bh / NHEADS;
    const int h = bh % NHEADS;

    const float* kp = g_k + (size_t)batch * L_ * H_ + h * DH;
    const float* vp = g_v + (size_t)batch * L_ * H_ + h * DH;
    for (int i = tid; i < L_ * (DH / 4); i += 128) {
        int l = i >> 4, c = i & 15;
        ((float4*)Ks)[i] = *(const float4*)(kp + (size_t)l * H_ + c * 4);
        ((float4*)Vs)[i] = *(const float4*)(vp + (size_t)l * H_ + c * 4);
    }
    __syncthreads();

    const int srow = blockIdx.x * 128 + tid;
    const float* qp = g_q + ((size_t)batch * S_ + srow) * H_ + h * DH;

    const uint64_t scale2 = pack2(0.125f);
    uint64_t qr2[32];
    #pragma unroll
    for (int c = 0; c < 16; c++) {
        ulonglong2 t = *(const ulonglong2*)(qp + c * 4);
        qr2[c * 2 + 0] = mul2(t.x, scale2);
        qr2[c * 2 + 1] = mul2(t.y, scale2);
    }

    uint64_t acc2[32];
    #pragma unroll
    for (int j = 0; j < 32; j++) acc2[j] = 0ull;
    float ssum = 0.f;

    for (int l = 0; l < L_; l++) {
        const ulonglong2* kk2 = (const ulonglong2*)&Ks[l * DH];
        uint64_t c0 = 0ull, c1 = 0ull, c2 = 0ull, c3 = 0ull;
        #pragma unroll
        for (int j = 0; j < 16; j += 2) {
            ulonglong2 t0 = kk2[j];
            ulonglong2 t1 = kk2[j + 1];
            c0 = fma2(qr2[2 * j + 0], t0.x, c0);
            c1 = fma2(qr2[2 * j + 1], t0.y, c1);
            c2 = fma2(qr2[2 * j + 2], t1.x, c2);
            c3 = fma2(qr2[2 * j + 3], t1.y, c3);
        }
        float s = hsum2(add2(add2(c0, c1), add2(c2, c3)));
        float p = __expf(s);
        ssum += p;
        uint64_t p2 = pack2(p);
        const ulonglong2* vv2 = (const ulonglong2*)&Vs[l * DH];
        #pragma unroll
        for (int j = 0; j < 16; j++) {
            ulonglong2 t = vv2[j];
            acc2[2 * j + 0] = fma2(p2, t.x, acc2[2 * j + 0]);
            acc2[2 * j + 1] = fma2(p2, t.y, acc2[2 * j + 1]);
        }
    }

    const uint64_t inv2 = pack2(1.f / ssum);
    size_t obase = ((size_t)batch * S_ + srow) * H_ + h * DH;
    #pragma unroll
    for (int j = 0; j < 32; j++) {
        uint64_t o2 = mul2(acc2[j], inv2);
        float2 f = *reinterpret_cast<float2*>(&o2);
        __nv_bfloat16 h0, l0, h1, l1;
        bf16split(f.x, h0, l0);
        bf16split(f.y, h1, l1);
        *(__nv_bfloat162*)(g_att_hi + obase + j * 2) = __nv_bfloat162(h0, h1);
        *(__nv_bfloat162*)(g_att_lo + obase + j * 2) = __nv_bfloat162(l0, l1);
    }
}

// ---------------------------------------------------------------------------
extern "C" void kernel_launch(void* const* d_in, const int* in_sizes, int n_in,
                              void* d_out, int out_size)
{
    (void)in_sizes; (void)n_in; (void)out_size;
    const float* hs    = (const float*)d_in[0];
    const float* ehs   = (const float*)d_in[1];
    const float* idemb = (const float*)d_in[2];
    const float* Wq    = (const float*)d_in[3];
    const float* Wk    = (const float*)d_in[4];
    const float* Wv    = (const float*)d_in[5];
    const float* Wid_k = (const float*)d_in[6];
    const float* Wid_v = (const float*)d_in[7];
    const float* Wout  = (const float*)d_in[8];
    const float* bout  = (const float*)d_in[9];
    float* out = (float*)d_out;

    const int attn_smem = 2 * L_ * DH * (int)sizeof(float);   // 55,808 B
    const int gemm_smem = NSTAGE * STAGE_B;                   // 73,728 B
    cudaFuncSetAttribute(attn_kernel,
                         cudaFuncAttributeMaxDynamicSharedMemorySize, attn_smem);
    cudaFuncSetAttribute(gemm_hmma<0>,
                         cudaFuncAttributeMaxDynamicSharedMemorySize, gemm_smem);
    cudaFuncSetAttribute(gemm_hmma<1>,
                         cudaFuncAttributeMaxDynamicSharedMemorySize, gemm_smem);

    // Prep: bf16 splits
    split_kernel<<<(ROWS * H_ / 4 + 255) / 256, 256>>>(hs);
    tsplit_kernel<<<dim3(H_ / 32, H_ / 32, 2), dim3(32, 8)>>>(Wq, Wout);

    // K/V projections
    kv_kernel<<<dim3(H_ / 64, (B_ * T_ + 63) / 64, 4), 256>>>(
        ehs, idemb, Wk, Wv, Wid_k, Wid_v);

    // q = hs @ Wq  (HMMA bf16x3)
    gemm_hmma<0><<<dim3(GN / 128, ROWS / TM), 256, gemm_smem>>>(nullptr, nullptr);

    // attention -> bf16 splits
    attn_kernel<<<dim3(S_ / 128, B_ * NHEADS), 128, attn_smem>>>();

    // out = att @ Wout + bout  (HMMA bf16x3)
    gemm_hmma<1><<<dim3(GN / 128, ROWS / TM), 256, gemm_smem>>>(bout, out);
}

// round 8
// speedup vs baseline: 1.0014x; 1.0014x over previous
#include <cuda_runtime.h>
#include <cuda_bf16.h>
#include <cstdint>
#include <math.h>

// Problem constants
#define B_      4
#define S_      4096
#define H_      1280
#define C_      2048
#define T_      77
#define I_      32
#define NHEADS  20
#define DH      64
#define L_      (T_ + I_)       // 109
#define ROWS    (B_ * S_)       // 16384

// ---------------------------------------------------------------------------
// Scratch (device globals; no allocations allowed)
// ---------------------------------------------------------------------------
__device__ float         g_q[ROWS * H_];        // q projection (fp32, read by attn)
__device__ __nv_bfloat16 g_att_hi[ROWS * H_];   // attention out, bf16 split
__device__ __nv_bfloat16 g_att_lo[ROWS * H_];
__device__ __nv_bfloat16 g_hs_hi[ROWS * H_];    // hidden_states, bf16 split
__device__ __nv_bfloat16 g_hs_lo[ROWS * H_];
__device__ __nv_bfloat16 g_wq_hi[H_ * H_];      // Wq^T [N,K], bf16 split
__device__ __nv_bfloat16 g_wq_lo[H_ * H_];
__device__ __nv_bfloat16 g_wo_hi[H_ * H_];      // Wout^T [N,K], bf16 split
__device__ __nv_bfloat16 g_wo_lo[H_ * H_];
__device__ float         g_k[B_ * L_ * H_];
__device__ float         g_v[B_ * L_ * H_];

// ---------------------------------------------------------------------------
// PTX helpers (sm_100 base target — NO tcgen05, which needs the 'a' variant)
// ---------------------------------------------------------------------------
#define CP_ASYNC_16(dst, src) \
    asm volatile("cp.async.cg.shared.global [%0], [%1], 16;" :: "r"(dst), "l"(src) : "memory")
#define CP_COMMIT() asm volatile("cp.async.commit_group;" ::: "memory")
#define CP_WAIT1()  asm volatile("cp.async.wait_group 1;" ::: "memory")

__device__ __forceinline__ uint32_t smem_to_u32(const void* p) {
    uint32_t a;
    asm("{ .reg .u64 t; cvta.to.shared.u64 t, %1; cvt.u32.u64 %0, t; }"
        : "=r"(a) : "l"(p));
    return a;
}

__device__ __forceinline__ void ldsm_x4(uint32_t& r0, uint32_t& r1,
                                        uint32_t& r2, uint32_t& r3, uint32_t addr) {
    asm volatile("ldmatrix.sync.aligned.m8n8.x4.shared.b16 {%0,%1,%2,%3}, [%4];"
                 : "=r"(r0), "=r"(r1), "=r"(r2), "=r"(r3) : "r"(addr));
}

__device__ __forceinline__ void mma_bf16(float* d, const uint32_t* a,
                                         uint32_t b0, uint32_t b1) {
    asm volatile(
        "mma.sync.aligned.m16n8k16.row.col.f32.bf16.bf16.f32 "
        "{%0,%1,%2,%3}, {%4,%5,%6,%7}, {%8,%9}, {%0,%1,%2,%3};"
        : "+f"(d[0]), "+f"(d[1]), "+f"(d[2]), "+f"(d[3])
        : "r"(a[0]), "r"(a[1]), "r"(a[2]), "r"(a[3]), "r"(b0), "r"(b1));
}

// Packed f32x2 ops (Blackwell, base sm_100 target)
__device__ __forceinline__ uint64_t fma2(uint64_t a, uint64_t b, uint64_t c) {
    uint64_t d;
    asm("fma.rn.f32x2 %0, %1, %2, %3;" : "=l"(d) : "l"(a), "l"(b), "l"(c));
    return d;
}
__device__ __forceinline__ uint64_t add2(uint64_t a, uint64_t b) {
    uint64_t d;
    asm("add.rn.f32x2 %0, %1, %2;" : "=l"(d) : "l"(a), "l"(b));
    return d;
}
__device__ __forceinline__ uint64_t mul2(uint64_t a, uint64_t b) {
    uint64_t d;
    asm("mul.rn.f32x2 %0, %1, %2;" : "=l"(d) : "l"(a), "l"(b));
    return d;
}
__device__ __forceinline__ uint64_t pack2(float x) {
    uint64_t d;
    uint32_t u = __float_as_uint(x);
    asm("mov.b64 %0, {%1, %1};" : "=l"(d) : "r"(u));
    return d;
}
__device__ __forceinline__ float hsum2(uint64_t v) {
    uint32_t lo, hi;
    asm("mov.b64 {%0, %1}, %2;" : "=r"(lo), "=r"(hi) : "l"(v));
    return __uint_as_float(lo) + __uint_as_float(hi);
}

// bf16 two-term split of fp32
__device__ __forceinline__ void bf16split(float x, __nv_bfloat16& h, __nv_bfloat16& l) {
    h = __float2bfloat16_rn(x);
    l = __float2bfloat16_rn(x - __bfloat162float(h));
}

// ---------------------------------------------------------------------------
// Prep 1: elementwise split of hidden_states -> g_hs_hi/lo
// ---------------------------------------------------------------------------
__global__ void __launch_bounds__(256) split_kernel(const float* __restrict__ src)
{
    size_t i = ((size_t)blockIdx.x * 256 + threadIdx.x) * 4;
    float4 v = *(const float4*)(src + i);
    __nv_bfloat16 h0, l0, h1, l1, h2, l2, h3, l3;
    bf16split(v.x, h0, l0); bf16split(v.y, h1, l1);
    bf16split(v.z, h2, l2); bf16split(v.w, h3, l3);
    *(__nv_bfloat162*)(g_hs_hi + i)     = __nv_bfloat162(h0, h1);
    *(__nv_bfloat162*)(g_hs_hi + i + 2) = __nv_bfloat162(h2, h3);
    *(__nv_bfloat162*)(g_hs_lo + i)     = __nv_bfloat162(l0, l1);
    *(__nv_bfloat162*)(g_hs_lo + i + 2) = __nv_bfloat162(l2, l3);
}

// ---------------------------------------------------------------------------
// Prep 2: transpose+split Wq and Wout -> [N, K] bf16 splits
// ---------------------------------------------------------------------------
__global__ void __launch_bounds__(256) tsplit_kernel(const float* __restrict__ Wq,
                                                     const float* __restrict__ Wout)
{
    __shared__ float t[32][33];
    const float* W = blockIdx.z ? Wout : Wq;
    __nv_bfloat16* dh = blockIdx.z ? g_wo_hi : g_wq_hi;
    __nv_bfloat16* dl = blockIdx.z ? g_wo_lo : g_wq_lo;
    int bx = blockIdx.x * 32, by = blockIdx.y * 32;
    int tx = threadIdx.x, ty = threadIdx.y;
    #pragma unroll
    for (int i = 0; i < 4; i++)
        t[ty + 8 * i][tx] = W[(size_t)(by + ty + 8 * i) * H_ + bx + tx];
    __syncthreads();
    #pragma unroll
    for (int i = 0; i < 4; i++) {
        float v = t[tx][ty + 8 * i];
        __nv_bfloat16 h, l;
        bf16split(v, h, l);
        size_t o = (size_t)(bx + ty + 8 * i) * H_ + by + tx;   // [n][k]
        dh[o] = h;
        dl[o] = l;
    }
}

// ---------------------------------------------------------------------------
// KV build: fp32 SIMT, small (436x1280x2048 effective)
// ---------------------------------------------------------------------------
__global__ void __launch_bounds__(256) kv_kernel(
    const float* __restrict__ ehs, const float* __restrict__ idemb,
    const float* __restrict__ Wk, const float* __restrict__ Wv,
    const float* __restrict__ Wid_k, const float* __restrict__ Wid_v)
{
    const int z = blockIdx.z;
    const bool is_id = (z >= 2);
    const bool is_v  = (z & 1);
    const float* A = is_id ? idemb : ehs;
    const float* W = is_id ? (is_v ? Wid_v : Wid_k) : (is_v ? Wv : Wk);
    float* outp = is_v ? g_v : g_k;
    const int Mloc = is_id ? (2 * I_) : (B_ * T_);

    const int m0 = blockIdx.y * 64;
    if (m0 >= Mloc) return;
    const int n0 = blockIdx.x * 64;

    __shared__ float As[16][68];
    __shared__ float Bs[16][64];

    const int tid  = threadIdx.x;
    const int arow = tid >> 2;
    const int ac4  = (tid & 3) * 4;
    const int brow = tid >> 4;
    const int bc4  = (tid & 15) * 4;
    const int tx   = tid & 15;
    const int ty   = tid >> 4;

    float acc[4][4];
    #pragma unroll
    for (int i = 0; i < 4; i++)
        #pragma unroll
        for (int j = 0; j < 4; j++) acc[i][j] = 0.f;

    for (int k0 = 0; k0 < C_; k0 += 16) {
        float4 av = make_float4(0.f, 0.f, 0.f, 0.f);
        if (m0 + arow < Mloc)
            av = *(const float4*)(A + (size_t)(m0 + arow) * C_ + k0 + ac4);
        float4 bv = *(const float4*)(W + (size_t)(k0 + brow) * H_ + n0 + bc4);
        __syncthreads();
        As[ac4 + 0][arow] = av.x;
        As[ac4 + 1][arow] = av.y;
        As[ac4 + 2][arow] = av.z;
        As[ac4 + 3][arow] = av.w;
        *(float4*)&Bs[brow][bc4] = bv;
        __syncthreads();
        #pragma unroll
        for (int kk = 0; kk < 16; kk++) {
            float4 a = *(const float4*)&As[kk][ty * 4];
            float4 b = *(const float4*)&Bs[kk][tx * 4];
            float am[4] = {a.x, a.y, a.z, a.w};
            float bn[4] = {b.x, b.y, b.z, b.w};
            #pragma unroll
            for (int i = 0; i < 4; i++)
                #pragma unroll
                for (int j = 0; j < 4; j++)
                    acc[i][j] += am[i] * bn[j];
        }
    }

    #pragma unroll
    for (int i = 0; i < 4; i++) {
        int r = m0 + ty * 4 + i;
        if (r >= Mloc) continue;
        float4 o = make_float4(acc[i][0], acc[i][1], acc[i][2], acc[i][3]);
        if (!is_id) {
            int batch = r / T_, pos = r % T_;
            *(float4*)(outp + (size_t)(batch * L_ + pos) * H_ + n0 + tx * 4) = o;
        } else {
            int hb = r >> 5, ii = r & 31;
            *(float4*)(outp + (size_t)( hb      * L_ + T_ + ii) * H_ + n0 + tx * 4) = o;
            *(float4*)(outp + (size_t)((hb + 2) * L_ + T_ + ii) * H_ + n0 + tx * 4) = o;
        }
    }
}

// ---------------------------------------------------------------------------
// HMMA bf16x3 GEMM (R6 config restored): CTA 128x128, BK=32, 8 warps (4x2),
// warp tile 32x64, 2 CTAs/SM, 3-stage cp.async, 1 barrier/iter.
// R8 change: refill is issued BEFORE the MMA section (safe: top-of-loop
// barrier guarantees stage (it+2)%3 was fully consumed at it-1), giving
// each cp.async a full extra iteration of latency slack.
// ---------------------------------------------------------------------------
#define GK       H_          // 1280
#define GN       H_          // 1280
#define BK       32
#define NIT      (GK / BK)   // 40
#define TILE_B   (128 * 64)  // 8192 B
#define STAGE_B  (4 * TILE_B)   // Ah, Al, Bh, Bl = 32768 B
#define NSTAGE   3

__device__ __forceinline__ uint32_t swz(int row, int chunk) {
    return (uint32_t)(row * 64 + ((chunk ^ ((row >> 1) & 3)) << 4));
}

__device__ __forceinline__ void fill_tile(uint32_t dst, const __nv_bfloat16* src,
                                          int k0, int tid)
{
    #pragma unroll
    for (int i = 0; i < 2; i++) {
        int idx = i * 256 + tid;         // 0..511
        int row = idx >> 2;              // 0..127
        int c   = idx & 3;               // 16B chunk (8 bf16)
        CP_ASYNC_16(dst + swz(row, c),
                    src + (size_t)row * GK + k0 + c * 8);
    }
}

template<int MODE>
__global__ void __launch_bounds__(256, 2) gemm_hmma(
    const float* __restrict__ bias, float* __restrict__ Cp)
{
    const __nv_bfloat16* Ahi = (MODE == 0) ? g_hs_hi : g_att_hi;
    const __nv_bfloat16* Alo = (MODE == 0) ? g_hs_lo : g_att_lo;
    const __nv_bfloat16* Bhi = (MODE == 0) ? g_wq_hi : g_wo_hi;
    const __nv_bfloat16* Blo = (MODE == 0) ? g_wq_lo : g_wo_lo;
    float* C = (MODE == 0) ? (float*)g_q : Cp;

    extern __shared__ char smem[];
    const uint32_t sb = smem_to_u32(smem);

    const int tid  = threadIdx.x;
    const int wid  = tid >> 5;
    const int lane = tid & 31;
    const int wm   = wid >> 1;          // 0..3 (M)
    const int wn   = wid & 1;           // 0..1 (N)
    const int n0 = blockIdx.x * 128;
    const int m0 = blockIdx.y * 128;

    const __nv_bfloat16* aH = Ahi + (size_t)m0 * GK;
    const __nv_bfloat16* aL = Alo + (size_t)m0 * GK;
    const __nv_bfloat16* bH = Bhi + (size_t)n0 * GK;
    const __nv_bfloat16* bL = Blo + (size_t)n0 * GK;

    const int a_row_off = (lane & 7) + ((lane >> 3) & 1) * 8;
    const int a_half    = lane >> 4;
    const int b_row_off = (lane & 7) + ((lane >> 4) & 1) * 8;
    const int b_half    = (lane >> 3) & 1;

    float acc[2][8][4];
    #pragma unroll
    for (int mt = 0; mt < 2; mt++)
        #pragma unroll
        for (int nt = 0; nt < 8; nt++)
            #pragma unroll
            for (int c = 0; c < 4; c++) acc[mt][nt][c] = 0.f;

    // Prologue: fill stages 0 and 1
    #pragma unroll
    for (int st = 0; st < 2; st++) {
        uint32_t s = sb + st * STAGE_B;
        fill_tile(s + 0 * TILE_B, aH, st * BK, tid);
        fill_tile(s + 1 * TILE_B, aL, st * BK, tid);
        fill_tile(s + 2 * TILE_B, bH, st * BK, tid);
        fill_tile(s + 3 * TILE_B, bL, st * BK, tid);
        CP_COMMIT();
    }

    int stage = 0;
    for (int it = 0; it < NIT; it++) {
        uint32_t s = sb + stage * STAGE_B;
        CP_WAIT1();
        __syncthreads();    // all warps done with stage (it+2)%3 (read at it-1)

        // R8: refill FIRST — loads drain while the tensor pipe runs below.
        if (it + 2 < NIT) {
            int fs = stage + 2 >= NSTAGE ? stage + 2 - NSTAGE : stage + 2;
            uint32_t f = sb + fs * STAGE_B;
            int k0 = (it + 2) * BK;
            fill_tile(f + 0 * TILE_B, aH, k0, tid);
            fill_tile(f + 1 * TILE_B, aL, k0, tid);
            fill_tile(f + 2 * TILE_B, bH, k0, tid);
            fill_tile(f + 3 * TILE_B, bL, k0, tid);
        }
        CP_COMMIT();   // empty group when no refill keeps wait_group exact

        const uint32_t sAh = s + 0 * TILE_B;
        const uint32_t sAl = s + 1 * TILE_B;
        const uint32_t sBh = s + 2 * TILE_B;
        const uint32_t sBl = s + 3 * TILE_B;

        #pragma unroll
        for (int ks = 0; ks < 2; ks++) {
            uint32_t fAh[2][4], fAl[2][4];
            #pragma unroll
            for (int mt = 0; mt < 2; mt++) {
                int row = wm * 32 + mt * 16 + a_row_off;
                uint32_t ad = swz(row, ks * 2 + a_half);
                ldsm_x4(fAh[mt][0], fAh[mt][1], fAh[mt][2], fAh[mt][3], sAh + ad);
                ldsm_x4(fAl[mt][0], fAl[mt][1], fAl[mt][2], fAl[mt][3], sAl + ad);
            }
            #pragma unroll
            for (int g = 0; g < 4; g++) {
                int row = wn * 64 + g * 16 + b_row_off;
                uint32_t bd = swz(row, ks * 2 + b_half);
                uint32_t b0, b1, b2, b3;
                ldsm_x4(b0, b1, b2, b3, sBh + bd);
                #pragma unroll
                for (int mt = 0; mt < 2; mt++) {
                    mma_bf16(acc[mt][g * 2 + 0], fAh[mt], b0, b1);
                    mma_bf16(acc[mt][g * 2 + 1], fAh[mt], b2, b3);
                    mma_bf16(acc[mt][g * 2 + 0], fAl[mt], b0, b1);
                    mma_bf16(acc[mt][g * 2 + 1], fAl[mt], b2, b3);
                }
            }
            #pragma unroll
            for (int g = 0; g < 4; g++) {
                int row = wn * 64 + g * 16 + b_row_off;
                uint32_t bd = swz(row, ks * 2 + b_half);
                uint32_t b0, b1, b2, b3;
                ldsm_x4(b0, b1, b2, b3, sBl + bd);
                #pragma unroll
                for (int mt = 0; mt < 2; mt++) {
                    mma_bf16(acc[mt][g * 2 + 0], fAh[mt], b0, b1);
                    mma_bf16(acc[mt][g * 2 + 1], fAh[mt], b2, b3);
                }
            }
        }

        stage = stage + 1 >= NSTAGE ? 0 : stage + 1;
    }

    // Epilogue: c-frag -> global fp32 (+bias)
    const int gid = lane >> 2, tig = lane & 3;
    #pragma unroll
    for (int mt = 0; mt < 2; mt++) {
        #pragma unroll
        for (int nt = 0; nt < 8; nt++) {
            int r   = m0 + wm * 32 + mt * 16 + gid;
            int col = n0 + wn * 64 + nt * 8 + tig * 2;
            float b0v = 0.f, b1v = 0.f;
            if (MODE == 1) { b0v = bias[col]; b1v = bias[col + 1]; }
            float2 v0 = make_float2(acc[mt][nt][0] + b0v, acc[mt][nt][1] + b1v);
            float2 v1 = make_float2(acc[mt][nt][2] + b0v, acc[mt][nt][3] + b1v);
            *(float2*)(C + (size_t)r * GN + col)       = v0;
            *(float2*)(C + (size_t)(r + 8) * GN + col) = v1;
        }
    }
}

// ---------------------------------------------------------------------------
// Attention, packed f32x2 (R6 version, 256 threads). Writes bf16 splits.
// ---------------------------------------------------------------------------
__global__ void __launch_bounds__(256) attn_kernel()
{
    extern __shared__ float asmem[];
    float* Ks = asmem;
    float* Vs = asmem + L_ * DH;

    const int tid = threadIdx.x;
    const int bh = blockIdx.y;
    const int batch = bh / NHEADS;
    const int h = bh % NHEADS;

    const float* kp = g_k + (size_t)batch * L_ * H_ + h * DH;
    const float* vp = g_v + (size_t)batch * L_ * H_ + h * DH;
    for (int i = tid; i < L_ * (DH / 4); i += 256) {
        int l = i >> 4, c = i & 15;
        ((float4*)Ks)[i] = *(const float4*)(kp + (size_t)l * H_ + c * 4);
        ((float4*)Vs)[i] = *(const float4*)(vp + (size_t)l * H_ + c * 4);
    }
    __syncthreads();

    const int srow = blockIdx.x * 256 + tid;
    const float* qp = g_q + ((size_t)batch * S_ + srow) * H_ + h * DH;

    const uint64_t scale2 = pack2(0.125f);
    uint64_t qr2[32];
    #pragma unroll
    for (int c = 0; c < 16; c++) {
        ulonglong2 t = *(const ulonglong2*)(qp + c * 4);
        qr2[c * 2 + 0] = mul2(t.x, scale2);
        qr2[c * 2 + 1] = mul2(t.y, scale2);
    }

    uint64_t acc2[32];
    #pragma unroll
    for (int j = 0; j < 32; j++) acc2[j] = 0ull;
    float ssum = 0.f;

    for (int l = 0; l < L_; l++) {
        const ulonglong2* kk2 = (const ulonglong2*)&Ks[l * DH];
        uint64_t c0 = 0ull, c1 = 0ull, c2 = 0ull, c3 = 0ull;
        #pragma unroll
        for (int j = 0; j < 16; j += 2) {
            ulonglong2 t0 = kk2[j];
            ulonglong2 t1 = kk2[j + 1];
            c0 = fma2(qr2[2 * j + 0], t0.x, c0);
            c1 = fma2(qr2[2 * j + 1], t0.y, c1);
            c2 = fma2(qr2[2 * j + 2], t1.x, c2);
            c3 = fma2(qr2[2 * j + 3], t1.y, c3);
        }
        float s = hsum2(add2(add2(c0, c1), add2(c2, c3)));
        float p = __expf(s);
        ssum += p;
        uint64_t p2 = pack2(p);
        const ulonglong2* vv2 = (const ulonglong2*)&Vs[l * DH];
        #pragma unroll
        for (int j = 0; j < 16; j++) {
            ulonglong2 t = vv2[j];
            acc2[2 * j + 0] = fma2(p2, t.x, acc2[2 * j + 0]);
            acc2[2 * j + 1] = fma2(p2, t.y, acc2[2 * j + 1]);
        }
    }

    const uint64_t inv2 = pack2(1.f / ssum);
    size_t obase = ((size_t)batch * S_ + srow) * H_ + h * DH;
    #pragma unroll
    for (int j = 0; j < 32; j++) {
        uint64_t o2 = mul2(acc2[j], inv2);
        float2 f = *reinterpret_cast<float2*>(&o2);
        __nv_bfloat16 h0, l0, h1, l1;
        bf16split(f.x, h0, l0);
        bf16split(f.y, h1, l1);
        *(__nv_bfloat162*)(g_att_hi + obase + j * 2) = __nv_bfloat162(h0, h1);
        *(__nv_bfloat162*)(g_att_lo + obase + j * 2) = __nv_bfloat162(l0, l1);
    }
}

// ---------------------------------------------------------------------------
extern "C" void kernel_launch(void* const* d_in, const int* in_sizes, int n_in,
                              void* d_out, int out_size)
{
    (void)in_sizes; (void)n_in; (void)out_size;
    const float* hs    = (const float*)d_in[0];
    const float* ehs   = (const float*)d_in[1];
    const float* idemb = (const float*)d_in[2];
    const float* Wq    = (const float*)d_in[3];
    const float* Wk    = (const float*)d_in[4];
    const float* Wv    = (const float*)d_in[5];
    const float* Wid_k = (const float*)d_in[6];
    const float* Wid_v = (const float*)d_in[7];
    const float* Wout  = (const float*)d_in[8];
    const float* bout  = (const float*)d_in[9];
    float* out = (float*)d_out;

    const int attn_smem = 2 * L_ * DH * (int)sizeof(float);   // 55,808 B
    const int gemm_smem = NSTAGE * STAGE_B;                   // 98,304 B
    cudaFuncSetAttribute(attn_kernel,
                         cudaFuncAttributeMaxDynamicSharedMemorySize, attn_smem);
    cudaFuncSetAttribute(gemm_hmma<0>,
                         cudaFuncAttributeMaxDynamicSharedMemorySize, gemm_smem);
    cudaFuncSetAttribute(gemm_hmma<1>,
                         cudaFuncAttributeMaxDynamicSharedMemorySize, gemm_smem);

    // Prep: bf16 splits
    split_kernel<<<(ROWS * H_ / 4 + 255) / 256, 256>>>(hs);
    tsplit_kernel<<<dim3(H_ / 32, H_ / 32, 2), dim3(32, 8)>>>(Wq, Wout);

    // K/V projections
    kv_kernel<<<dim3(H_ / 64, (B_ * T_ + 63) / 64, 4), 256>>>(
        ehs, idemb, Wk, Wv, Wid_k, Wid_v);

    // q = hs @ Wq  (HMMA bf16x3)
    gemm_hmma<0><<<dim3(GN / 128, ROWS / 128), 256, gemm_smem>>>(nullptr, nullptr);

    // attention -> bf16 splits
    attn_kernel<<<dim3(S_ / 256, B_ * NHEADS), 256, attn_smem>>>();

    // out = att @ Wout + bout  (HMMA bf16x3)
    gemm_hmma<1><<<dim3(GN / 128, ROWS / 128), 256, gemm_smem>>>(bout, out);
}

// round 9
// speedup vs baseline: 1.3291x; 1.3272x over previous
#include <cuda_runtime.h>
#include <cuda_bf16.h>
#include <cstdint>
#include <math.h>

// Problem constants
#define B_      4
#define S_      4096
#define H_      1280
#define C_      2048
#define T_      77
#define I_      32
#define NHEADS  20
#define DH      64
#define L_      (T_ + I_)       // 109
#define LPAD    112             // K rows padded (mult of 16)
#define LPAD2   120             // V^T row length (240B rows -> conflict-free)
#define ROWS    (B_ * S_)       // 16384

// ---------------------------------------------------------------------------
// Scratch (device globals; zero-initialized; no allocations allowed)
// ---------------------------------------------------------------------------
__device__ __nv_bfloat16 g_q_hi[ROWS * H_];     // q projection, bf16 split
__device__ __nv_bfloat16 g_q_lo[ROWS * H_];
__device__ __nv_bfloat16 g_att_hi[ROWS * H_];   // attention out, bf16 split
__device__ __nv_bfloat16 g_att_lo[ROWS * H_];
__device__ __nv_bfloat16 g_hs_hi[ROWS * H_];    // hidden_states, bf16 split
__device__ __nv_bfloat16 g_hs_lo[ROWS * H_];
__device__ __nv_bfloat16 g_wq_hi[H_ * H_];      // Wq^T [N,K], bf16 split
__device__ __nv_bfloat16 g_wq_lo[H_ * H_];
__device__ __nv_bfloat16 g_wo_hi[H_ * H_];      // Wout^T [N,K], bf16 split
__device__ __nv_bfloat16 g_wo_lo[H_ * H_];
__device__ __nv_bfloat16 g_k_hi[B_ * LPAD * H_];   // K [b][l][n], rows 109..111 zero
__device__ __nv_bfloat16 g_k_lo[B_ * LPAD * H_];
__device__ __nv_bfloat16 g_vt_hi[B_ * H_ * LPAD2]; // V^T [b][n][l], l 109..119 zero
__device__ __nv_bfloat16 g_vt_lo[B_ * H_ * LPAD2];

// ---------------------------------------------------------------------------
// PTX helpers (sm_100 base target — NO tcgen05, which needs the 'a' variant)
// ---------------------------------------------------------------------------
#define CP_ASYNC_16(dst, src) \
    asm volatile("cp.async.cg.shared.global [%0], [%1], 16;" :: "r"(dst), "l"(src) : "memory")
#define CP_COMMIT() asm volatile("cp.async.commit_group;" ::: "memory")
#define CP_WAIT1()  asm volatile("cp.async.wait_group 1;" ::: "memory")
#define CP_WAIT0()  asm volatile("cp.async.wait_group 0;" ::: "memory")

__device__ __forceinline__ uint32_t smem_to_u32(const void* p) {
    uint32_t a;
    asm("{ .reg .u64 t; cvta.to.shared.u64 t, %1; cvt.u32.u64 %0, t; }"
        : "=r"(a) : "l"(p));
    return a;
}

__device__ __forceinline__ void ldsm_x4(uint32_t& r0, uint32_t& r1,
                                        uint32_t& r2, uint32_t& r3, uint32_t addr) {
    asm volatile("ldmatrix.sync.aligned.m8n8.x4.shared.b16 {%0,%1,%2,%3}, [%4];"
                 : "=r"(r0), "=r"(r1), "=r"(r2), "=r"(r3) : "r"(addr));
}

__device__ __forceinline__ void mma_bf16(float* d, const uint32_t* a,
                                         uint32_t b0, uint32_t b1) {
    asm volatile(
        "mma.sync.aligned.m16n8k16.row.col.f32.bf16.bf16.f32 "
        "{%0,%1,%2,%3}, {%4,%5,%6,%7}, {%8,%9}, {%0,%1,%2,%3};"
        : "+f"(d[0]), "+f"(d[1]), "+f"(d[2]), "+f"(d[3])
        : "r"(a[0]), "r"(a[1]), "r"(a[2]), "r"(a[3]), "r"(b0), "r"(b1));
}

// pack two fp32 -> bf16x2 reg {lo, hi}
__device__ __forceinline__ uint32_t pack_bf16x2(float lo, float hi) {
    uint32_t r;
    asm("cvt.rn.bf16x2.f32 %0, %1, %2;" : "=r"(r) : "f"(hi), "f"(lo));
    return r;
}
__device__ __forceinline__ void unpack_bf16x2(uint32_t v, float& lo, float& hi) {
    __nv_bfloat162 b = *reinterpret_cast<__nv_bfloat162*>(&v);
    lo = __bfloat162float(b.x);
    hi = __bfloat162float(b.y);
}

// bf16 two-term split of fp32
__device__ __forceinline__ void bf16split(float x, __nv_bfloat16& h, __nv_bfloat16& l) {
    h = __float2bfloat16_rn(x);
    l = __float2bfloat16_rn(x - __bfloat162float(h));
}

// ---------------------------------------------------------------------------
// Prep 1: elementwise split of hidden_states -> g_hs_hi/lo
// ---------------------------------------------------------------------------
__global__ void __launch_bounds__(256) split_kernel(const float* __restrict__ src)
{
    size_t i = ((size_t)blockIdx.x * 256 + threadIdx.x) * 4;
    float4 v = *(const float4*)(src + i);
    __nv_bfloat16 h0, l0, h1, l1, h2, l2, h3, l3;
    bf16split(v.x, h0, l0); bf16split(v.y, h1, l1);
    bf16split(v.z, h2, l2); bf16split(v.w, h3, l3);
    *(__nv_bfloat162*)(g_hs_hi + i)     = __nv_bfloat162(h0, h1);
    *(__nv_bfloat162*)(g_hs_hi + i + 2) = __nv_bfloat162(h2, h3);
    *(__nv_bfloat162*)(g_hs_lo + i)     = __nv_bfloat162(l0, l1);
    *(__nv_bfloat162*)(g_hs_lo + i + 2) = __nv_bfloat162(l2, l3);
}

// ---------------------------------------------------------------------------
// Prep 2: transpose+split Wq and Wout -> [N, K] bf16 splits
// ---------------------------------------------------------------------------
__global__ void __launch_bounds__(256) tsplit_kernel(const float* __restrict__ Wq,
                                                     const float* __restrict__ Wout)
{
    __shared__ float t[32][33];
    const float* W = blockIdx.z ? Wout : Wq;
    __nv_bfloat16* dh = blockIdx.z ? g_wo_hi : g_wq_hi;
    __nv_bfloat16* dl = blockIdx.z ? g_wo_lo : g_wq_lo;
    int bx = blockIdx.x * 32, by = blockIdx.y * 32;
    int tx = threadIdx.x, ty = threadIdx.y;
    #pragma unroll
    for (int i = 0; i < 4; i++)
        t[ty + 8 * i][tx] = W[(size_t)(by + ty + 8 * i) * H_ + bx + tx];
    __syncthreads();
    #pragma unroll
    for (int i = 0; i < 4; i++) {
        float v = t[tx][ty + 8 * i];
        __nv_bfloat16 h, l;
        bf16split(v, h, l);
        size_t o = (size_t)(bx + ty + 8 * i) * H_ + by + tx;   // [n][k]
        dh[o] = h;
        dl[o] = l;
    }
}

// ---------------------------------------------------------------------------
// KV build: fp32 SIMT GEMM; outputs bf16 splits.
// K -> [b][LPAD][H_] (row-major), V -> transposed [b][H_][LPAD2] for HMMA PV.
// ---------------------------------------------------------------------------
__device__ __forceinline__ void kv_store(bool is_v, int b, int l, int n,
                                         const float* vals)
{
    __nv_bfloat16 hi[4], lo[4];
    #pragma unroll
    for (int j = 0; j < 4; j++) bf16split(vals[j], hi[j], lo[j]);
    if (!is_v) {
        size_t a = ((size_t)b * LPAD + l) * H_ + n;
        *(__nv_bfloat162*)(g_k_hi + a)     = __nv_bfloat162(hi[0], hi[1]);
        *(__nv_bfloat162*)(g_k_hi + a + 2) = __nv_bfloat162(hi[2], hi[3]);
        *(__nv_bfloat162*)(g_k_lo + a)     = __nv_bfloat162(lo[0], lo[1]);
        *(__nv_bfloat162*)(g_k_lo + a + 2) = __nv_bfloat162(lo[2], lo[3]);
    } else {
        #pragma unroll
        for (int j = 0; j < 4; j++) {
            size_t a = ((size_t)b * H_ + n + j) * LPAD2 + l;
            g_vt_hi[a] = hi[j];
            g_vt_lo[a] = lo[j];
        }
    }
}

__global__ void __launch_bounds__(256) kv_kernel(
    const float* __restrict__ ehs, const float* __restrict__ idemb,
    const float* __restrict__ Wk, const float* __restrict__ Wv,
    const float* __restrict__ Wid_k, const float* __restrict__ Wid_v)
{
    const int z = blockIdx.z;
    const bool is_id = (z >= 2);
    const bool is_v  = (z & 1);
    const float* A = is_id ? idemb : ehs;
    const float* W = is_id ? (is_v ? Wid_v : Wid_k) : (is_v ? Wv : Wk);
    const int Mloc = is_id ? (2 * I_) : (B_ * T_);

    const int m0 = blockIdx.y * 64;
    if (m0 >= Mloc) return;
    const int n0 = blockIdx.x * 64;

    __shared__ float As[16][68];
    __shared__ float Bs[16][64];

    const int tid  = threadIdx.x;
    const int arow = tid >> 2;
    const int ac4  = (tid & 3) * 4;
    const int brow = tid >> 4;
    const int bc4  = (tid & 15) * 4;
    const int tx   = tid & 15;
    const int ty   = tid >> 4;

    float acc[4][4];
    #pragma unroll
    for (int i = 0; i < 4; i++)
        #pragma unroll
        for (int j = 0; j < 4; j++) acc[i][j] = 0.f;

    for (int k0 = 0; k0 < C_; k0 += 16) {
        float4 av = make_float4(0.f, 0.f, 0.f, 0.f);
        if (m0 + arow < Mloc)
            av = *(const float4*)(A + (size_t)(m0 + arow) * C_ + k0 + ac4);
        float4 bv = *(const float4*)(W + (size_t)(k0 + brow) * H_ + n0 + bc4);
        __syncthreads();
        As[ac4 + 0][arow] = av.x;
        As[ac4 + 1][arow] = av.y;
        As[ac4 + 2][arow] = av.z;
        As[ac4 + 3][arow] = av.w;
        *(float4*)&Bs[brow][bc4] = bv;
        __syncthreads();
        #pragma unroll
        for (int kk = 0; kk < 16; kk++) {
            float4 a = *(const float4*)&As[kk][ty * 4];
            float4 b = *(const float4*)&Bs[kk][tx * 4];
            float am[4] = {a.x, a.y, a.z, a.w};
            float bn[4] = {b.x, b.y, b.z, b.w};
            #pragma unroll
            for (int i = 0; i < 4; i++)
                #pragma unroll
                for (int j = 0; j < 4; j++)
                    acc[i][j] += am[i] * bn[j];
        }
    }

    #pragma unroll
    for (int i = 0; i < 4; i++) {
        int r = m0 + ty * 4 + i;
        if (r >= Mloc) continue;
        if (!is_id) {
            int batch = r / T_, pos = r % T_;
            kv_store(is_v, batch, pos, n0 + tx * 4, acc[i]);
        } else {
            int hb = r >> 5, ii = r & 31;
            kv_store(is_v, hb,     T_ + ii, n0 + tx * 4, acc[i]);
            kv_store(is_v, hb + 2, T_ + ii, n0 + tx * 4, acc[i]);
        }
    }
}

// ---------------------------------------------------------------------------
// HMMA bf16x3 GEMM (R6 ordering — MMA first, refill after; 393us proven).
// CTA 128x128, BK=32, 8 warps (4x2), warp tile 32x64, 2 CTAs/SM, 3 stages.
// MODE 0: A=g_hs B=g_wq -> writes bf16 splits to g_q_hi/lo
// MODE 1: A=g_att B=g_wo -> writes fp32 + bias to Cp
// ---------------------------------------------------------------------------
#define GK       H_          // 1280
#define GN       H_          // 1280
#define BK       32
#define NIT      (GK / BK)   // 40
#define TILE_B   (128 * 64)  // 8192 B
#define STAGE_B  (4 * TILE_B)
#define NSTAGE   3

__device__ __forceinline__ uint32_t swz(int row, int chunk) {
    return (uint32_t)(row * 64 + ((chunk ^ ((row >> 1) & 3)) << 4));
}

__device__ __forceinline__ void fill_tile(uint32_t dst, const __nv_bfloat16* src,
                                          int k0, int tid)
{
    #pragma unroll
    for (int i = 0; i < 2; i++) {
        int idx = i * 256 + tid;
        int row = idx >> 2;
        int c   = idx & 3;
        CP_ASYNC_16(dst + swz(row, c),
                    src + (size_t)row * GK + k0 + c * 8);
    }
}

template<int MODE>
__global__ void __launch_bounds__(256, 2) gemm_hmma(
    const float* __restrict__ bias, float* __restrict__ Cp)
{
    const __nv_bfloat16* Ahi = (MODE == 0) ? g_hs_hi : g_att_hi;
    const __nv_bfloat16* Alo = (MODE == 0) ? g_hs_lo : g_att_lo;
    const __nv_bfloat16* Bhi = (MODE == 0) ? g_wq_hi : g_wo_hi;
    const __nv_bfloat16* Blo = (MODE == 0) ? g_wq_lo : g_wo_lo;

    extern __shared__ char smem[];
    const uint32_t sb = smem_to_u32(smem);

    const int tid  = threadIdx.x;
    const int wid  = tid >> 5;
    const int lane = tid & 31;
    const int wm   = wid >> 1;
    const int wn   = wid & 1;
    const int n0 = blockIdx.x * 128;
    const int m0 = blockIdx.y * 128;

    const __nv_bfloat16* aH = Ahi + (size_t)m0 * GK;
    const __nv_bfloat16* aL = Alo + (size_t)m0 * GK;
    const __nv_bfloat16* bH = Bhi + (size_t)n0 * GK;
    const __nv_bfloat16* bL = Blo + (size_t)n0 * GK;

    const int a_row_off = (lane & 7) + ((lane >> 3) & 1) * 8;
    const int a_half    = lane >> 4;
    const int b_row_off = (lane & 7) + ((lane >> 4) & 1) * 8;
    const int b_half    = (lane >> 3) & 1;

    float acc[2][8][4];
    #pragma unroll
    for (int mt = 0; mt < 2; mt++)
        #pragma unroll
        for (int nt = 0; nt < 8; nt++)
            #pragma unroll
            for (int c = 0; c < 4; c++) acc[mt][nt][c] = 0.f;

    #pragma unroll
    for (int st = 0; st < 2; st++) {
        uint32_t s = sb + st * STAGE_B;
        fill_tile(s + 0 * TILE_B, aH, st * BK, tid);
        fill_tile(s + 1 * TILE_B, aL, st * BK, tid);
        fill_tile(s + 2 * TILE_B, bH, st * BK, tid);
        fill_tile(s + 3 * TILE_B, bL, st * BK, tid);
        CP_COMMIT();
    }

    int stage = 0;
    for (int it = 0; it < NIT; it++) {
        uint32_t s = sb + stage * STAGE_B;
        CP_WAIT1();
        __syncthreads();

        const uint32_t sAh = s + 0 * TILE_B;
        const uint32_t sAl = s + 1 * TILE_B;
        const uint32_t sBh = s + 2 * TILE_B;
        const uint32_t sBl = s + 3 * TILE_B;

        #pragma unroll
        for (int ks = 0; ks < 2; ks++) {
            uint32_t fAh[2][4], fAl[2][4];
            #pragma unroll
            for (int mt = 0; mt < 2; mt++) {
                int row = wm * 32 + mt * 16 + a_row_off;
                uint32_t ad = swz(row, ks * 2 + a_half);
                ldsm_x4(fAh[mt][0], fAh[mt][1], fAh[mt][2], fAh[mt][3], sAh + ad);
                ldsm_x4(fAl[mt][0], fAl[mt][1], fAl[mt][2], fAl[mt][3], sAl + ad);
            }
            #pragma unroll
            for (int g = 0; g < 4; g++) {
                int row = wn * 64 + g * 16 + b_row_off;
                uint32_t bd = swz(row, ks * 2 + b_half);
                uint32_t b0, b1, b2, b3;
                ldsm_x4(b0, b1, b2, b3, sBh + bd);
                #pragma unroll
                for (int mt = 0; mt < 2; mt++) {
                    mma_bf16(acc[mt][g * 2 + 0], fAh[mt], b0, b1);
                    mma_bf16(acc[mt][g * 2 + 1], fAh[mt], b2, b3);
                    mma_bf16(acc[mt][g * 2 + 0], fAl[mt], b0, b1);
                    mma_bf16(acc[mt][g * 2 + 1], fAl[mt], b2, b3);
                }
            }
            #pragma unroll
            for (int g = 0; g < 4; g++) {
                int row = wn * 64 + g * 16 + b_row_off;
                uint32_t bd = swz(row, ks * 2 + b_half);
                uint32_t b0, b1, b2, b3;
                ldsm_x4(b0, b1, b2, b3, sBl + bd);
                #pragma unroll
                for (int mt = 0; mt < 2; mt++) {
                    mma_bf16(acc[mt][g * 2 + 0], fAh[mt], b0, b1);
                    mma_bf16(acc[mt][g * 2 + 1], fAh[mt], b2, b3);
                }
            }
        }

        if (it + 2 < NIT) {
            int fs = stage + 2 >= NSTAGE ? stage + 2 - NSTAGE : stage + 2;
            uint32_t f = sb + fs * STAGE_B;
            int k0 = (it + 2) * BK;
            fill_tile(f + 0 * TILE_B, aH, k0, tid);
            fill_tile(f + 1 * TILE_B, aL, k0, tid);
            fill_tile(f + 2 * TILE_B, bH, k0, tid);
            fill_tile(f + 3 * TILE_B, bL, k0, tid);
        }
        CP_COMMIT();
        stage = stage + 1 >= NSTAGE ? 0 : stage + 1;
    }

    // Epilogue
    const int gid = lane >> 2, tig = lane & 3;
    #pragma unroll
    for (int mt = 0; mt < 2; mt++) {
        #pragma unroll
        for (int nt = 0; nt < 8; nt++) {
            int r   = m0 + wm * 32 + mt * 16 + gid;
            int col = n0 + wn * 64 + nt * 8 + tig * 2;
            if (MODE == 0) {
                // write bf16 splits to g_q_hi/lo
                #pragma unroll
                for (int half = 0; half < 2; half++) {
                    int rr = r + half * 8;
                    __nv_bfloat16 h0, l0, h1, l1;
                    bf16split(acc[mt][nt][half * 2 + 0], h0, l0);
                    bf16split(acc[mt][nt][half * 2 + 1], h1, l1);
                    size_t a = (size_t)rr * GN + col;
                    *(__nv_bfloat162*)(g_q_hi + a) = __nv_bfloat162(h0, h1);
                    *(__nv_bfloat162*)(g_q_lo + a) = __nv_bfloat162(l0, l1);
                }
            } else {
                float b0v = bias[col], b1v = bias[col + 1];
                float2 v0 = make_float2(acc[mt][nt][0] + b0v, acc[mt][nt][1] + b1v);
                float2 v1 = make_float2(acc[mt][nt][2] + b0v, acc[mt][nt][3] + b1v);
                *(float2*)(Cp + (size_t)r * GN + col)       = v0;
                *(float2*)(Cp + (size_t)(r + 8) * GN + col) = v1;
            }
        }
    }
}

// ---------------------------------------------------------------------------
// HMMA flash attention. CTA = 128 queries x one (b,h). 8 warps x 16 rows.
// QK: A=q (splits, ldsm), B=K [l][d] row-major (non-trans ldsm, like gemm B).
// Softmax: no max-sub; exp; quad shfl row-sum; normalize at end.
// PV: A=p (C-frag repack, 3 products with p/v splits), B=V^T [d][l] non-trans.
// Smem: Qh/Ql 128x128B swz | Kh/Kl 112x128B swz | Vh/Vl 64x240B natural.
// ---------------------------------------------------------------------------
#define ASM_Q   0
#define ASM_K   (2 * 128 * 128)                 // 32768
#define ASM_V   (ASM_K + 2 * LPAD * 128)        // 32768 + 28672 = 61440
#define ASM_TOT (ASM_V + 2 * 64 * 240)          // 61440 + 30720 = 92160

__device__ __forceinline__ uint32_t swz128(int row, int chunk) {
    return (uint32_t)(row * 128 + ((chunk ^ (row & 7)) << 4));
}

__global__ void __launch_bounds__(256, 2) attn_kernel()
{
    extern __shared__ char asmem[];
    const uint32_t sb = smem_to_u32(asmem);
    const uint32_t sQh = sb + ASM_Q,  sQl = sQh + 128 * 128;
    const uint32_t sKh = sb + ASM_K,  sKl = sKh + LPAD * 128;
    const uint32_t sVh = sb + ASM_V,  sVl = sVh + 64 * 240;

    const int tid  = threadIdx.x;
    const int wid  = tid >> 5;
    const int lane = tid & 31;
    const int bh = blockIdx.y;
    const int batch = bh / NHEADS;
    const int h = bh % NHEADS;
    const int qrow0 = batch * S_ + blockIdx.x * 128;

    // ---- loads (one-shot, cp.async) ----
    {
        const __nv_bfloat16* qh = g_q_hi + (size_t)qrow0 * H_ + h * DH;
        const __nv_bfloat16* ql = g_q_lo + (size_t)qrow0 * H_ + h * DH;
        #pragma unroll
        for (int i = 0; i < 4; i++) {
            int idx = i * 256 + tid;            // 0..1023
            int row = idx >> 3, c = idx & 7;
            CP_ASYNC_16(sQh + swz128(row, c), qh + (size_t)row * H_ + c * 8);
            CP_ASYNC_16(sQl + swz128(row, c), ql + (size_t)row * H_ + c * 8);
        }
        const __nv_bfloat16* kh = g_k_hi + (size_t)batch * LPAD * H_ + h * DH;
        const __nv_bfloat16* kl = g_k_lo + (size_t)batch * LPAD * H_ + h * DH;
        for (int idx = tid; idx < LPAD * 8; idx += 256) {
            int row = idx >> 3, c = idx & 7;
            CP_ASYNC_16(sKh + swz128(row, c), kh + (size_t)row * H_ + c * 8);
            CP_ASYNC_16(sKl + swz128(row, c), kl + (size_t)row * H_ + c * 8);
        }
        const __nv_bfloat16* vh = g_vt_hi + ((size_t)batch * H_ + h * DH) * LPAD2;
        const __nv_bfloat16* vl = g_vt_lo + ((size_t)batch * H_ + h * DH) * LPAD2;
        for (int idx = tid; idx < 64 * 14; idx += 256) {
            int row = idx / 14, c = idx % 14;
            CP_ASYNC_16(sVh + (uint32_t)(row * 240 + c * 16),
                        vh + (size_t)row * LPAD2 + c * 8);
            CP_ASYNC_16(sVl + (uint32_t)(row * 240 + c * 16),
                        vl + (size_t)row * LPAD2 + c * 8);
        }
        CP_COMMIT();
    }
    CP_WAIT0();
    __syncthreads();

    const int gid = lane >> 2, tig = lane & 3;
    const int a_row_off = (lane & 7) + ((lane >> 3) & 1) * 8;
    const int a_half    = lane >> 4;
    const int b_row_off = (lane & 7) + ((lane >> 4) & 1) * 8;
    const int b_half    = (lane >> 3) & 1;

    // q fragments (held across the l-loop): 4 k-steps x hi/lo
    uint32_t fQh[4][4], fQl[4][4];
    #pragma unroll
    for (int ks = 0; ks < 4; ks++) {
        int row = wid * 16 + a_row_off;
        uint32_t ad = swz128(row, ks * 2 + a_half);
        ldsm_x4(fQh[ks][0], fQh[ks][1], fQh[ks][2], fQh[ks][3], sQh + ad);
        ldsm_x4(fQl[ks][0], fQl[ks][1], fQl[ks][2], fQl[ks][3], sQl + ad);
    }

    float acc[8][4];
    #pragma unroll
    for (int nt = 0; nt < 8; nt++)
        #pragma unroll
        for (int c = 0; c < 4; c++) acc[nt][c] = 0.f;
    float rs0 = 0.f, rs1 = 0.f;
    const float scale = 0.125f;

    #pragma unroll
    for (int kt = 0; kt < 7; kt++) {       // l tiles of 16 (0..111)
        // --- QK scores for n-tiles 2kt, 2kt+1 ---
        float c0[4] = {0.f, 0.f, 0.f, 0.f};
        float c1[4] = {0.f, 0.f, 0.f, 0.f};
        #pragma unroll
        for (int ks = 0; ks < 4; ks++) {
            int row = kt * 16 + b_row_off;
            uint32_t bd = swz128(row, ks * 2 + b_half);
            uint32_t kb0, kb1, kb2, kb3, kl0, kl1, kl2, kl3;
            ldsm_x4(kb0, kb1, kb2, kb3, sKh + bd);
            ldsm_x4(kl0, kl1, kl2, kl3, sKl + bd);
            mma_bf16(c0, fQh[ks], kb0, kb1);
            mma_bf16(c1, fQh[ks], kb2, kb3);
            mma_bf16(c0, fQh[ks], kl0, kl1);
            mma_bf16(c1, fQh[ks], kl2, kl3);
            mma_bf16(c0, fQl[ks], kb0, kb1);
            mma_bf16(c1, fQl[ks], kb2, kb3);
        }
        // --- exp + mask + row sums ---
        float e0[4], e1[4];
        #pragma unroll
        for (int j = 0; j < 4; j++) {
            e0[j] = __expf(c0[j] * scale);
            e1[j] = __expf(c1[j] * scale);
        }
        if (kt == 6) {   // n-tile 13: cols 104..111, mask col >= 109
            float m0v = (104 + 2 * tig <= 108) ? 1.f : 0.f;
            float m1v = (105 + 2 * tig <= 108) ? 1.f : 0.f;
            e1[0] *= m0v; e1[1] *= m1v; e1[2] *= m0v; e1[3] *= m1v;
        }
        rs0 += e0[0] + e0[1] + e1[0] + e1[1];
        rs1 += e0[2] + e0[3] + e1[2] + e1[3];
        // --- p fragments (FA2 C->A repack) + lo split ---
        uint32_t ah[4], al[4];
        ah[0] = pack_bf16x2(e0[0], e0[1]);
        ah[1] = pack_bf16x2(e0[2], e0[3]);
        ah[2] = pack_bf16x2(e1[0], e1[1]);
        ah[3] = pack_bf16x2(e1[2], e1[3]);
        {
            float f0, f1;
            unpack_bf16x2(ah[0], f0, f1); al[0] = pack_bf16x2(e0[0] - f0, e0[1] - f1);
            unpack_bf16x2(ah[1], f0, f1); al[1] = pack_bf16x2(e0[2] - f0, e0[3] - f1);
            unpack_bf16x2(ah[2], f0, f1); al[2] = pack_bf16x2(e1[0] - f0, e1[1] - f1);
            unpack_bf16x2(ah[3], f0, f1); al[3] = pack_bf16x2(e1[2] - f0, e1[3] - f1);
        }
        // --- PV: acc += p @ V^T-tile (k16 = these 16 l's) ---
        #pragma unroll
        for (int g = 0; g < 4; g++) {
            uint32_t bd = (uint32_t)((g * 16 + b_row_off) * 240 +
                                     (kt * 2 + b_half) * 16);
            uint32_t vb0, vb1, vb2, vb3, vl0, vl1, vl2, vl3;
            ldsm_x4(vb0, vb1, vb2, vb3, sVh + bd);
            ldsm_x4(vl0, vl1, vl2, vl3, sVl + bd);
            mma_bf16(acc[g * 2 + 0], ah, vb0, vb1);
            mma_bf16(acc[g * 2 + 1], ah, vb2, vb3);
            mma_bf16(acc[g * 2 + 0], al, vb0, vb1);
            mma_bf16(acc[g * 2 + 1], al, vb2, vb3);
            mma_bf16(acc[g * 2 + 0], ah, vl0, vl1);
            mma_bf16(acc[g * 2 + 1], ah, vl2, vl3);
        }
    }

    // quad reduction of row sums (lanes sharing gid differ only in tig)
    rs0 += __shfl_xor_sync(0xffffffffu, rs0, 1);
    rs0 += __shfl_xor_sync(0xffffffffu, rs0, 2);
    rs1 += __shfl_xor_sync(0xffffffffu, rs1, 1);
    rs1 += __shfl_xor_sync(0xffffffffu, rs1, 2);
    const float inv0 = 1.f / rs0;
    const float inv1 = 1.f / rs1;

    // epilogue: normalize, split, store to g_att_hi/lo
    const int r0 = qrow0 + wid * 16 + gid;
    #pragma unroll
    for (int nt = 0; nt < 8; nt++) {
        int col = h * DH + nt * 8 + tig * 2;
        __nv_bfloat16 h0, l0, h1, l1;
        bf16split(acc[nt][0] * inv0, h0, l0);
        bf16split(acc[nt][1] * inv0, h1, l1);
        size_t a = (size_t)r0 * H_ + col;
        *(__nv_bfloat162*)(g_att_hi + a) = __nv_bfloat162(h0, h1);
        *(__nv_bfloat162*)(g_att_lo + a) = __nv_bfloat162(l0, l1);
        bf16split(acc[nt][2] * inv1, h0, l0);
        bf16split(acc[nt][3] * inv1, h1, l1);
        a = (size_t)(r0 + 8) * H_ + col;
        *(__nv_bfloat162*)(g_att_hi + a) = __nv_bfloat162(h0, h1);
        *(__nv_bfloat162*)(g_att_lo + a) = __nv_bfloat162(l0, l1);
    }
}

// ---------------------------------------------------------------------------
extern "C" void kernel_launch(void* const* d_in, const int* in_sizes, int n_in,
                              void* d_out, int out_size)
{
    (void)in_sizes; (void)n_in; (void)out_size;
    const float* hs    = (const float*)d_in[0];
    const float* ehs   = (const float*)d_in[1];
    const float* idemb = (const float*)d_in[2];
    const float* Wq    = (const float*)d_in[3];
    const float* Wk    = (const float*)d_in[4];
    const float* Wv    = (const float*)d_in[5];
    const float* Wid_k = (const float*)d_in[6];
    const float* Wid_v = (const float*)d_in[7];
    const float* Wout  = (const float*)d_in[8];
    const float* bout  = (const float*)d_in[9];
    float* out = (float*)d_out;

    const int attn_smem = ASM_TOT;            // 92,160 B
    const int gemm_smem = NSTAGE * STAGE_B;   // 98,304 B
    cudaFuncSetAttribute(attn_kernel,
                         cudaFuncAttributeMaxDynamicSharedMemorySize, attn_smem);
    cudaFuncSetAttribute(gemm_hmma<0>,
                         cudaFuncAttributeMaxDynamicSharedMemorySize, gemm_smem);
    cudaFuncSetAttribute(gemm_hmma<1>,
                         cudaFuncAttributeMaxDynamicSharedMemorySize, gemm_smem);

    // Prep: bf16 splits
    split_kernel<<<(ROWS * H_ / 4 + 255) / 256, 256>>>(hs);
    tsplit_kernel<<<dim3(H_ / 32, H_ / 32, 2), dim3(32, 8)>>>(Wq, Wout);

    // K/V projections -> bf16 splits (K row-major, V transposed)
    kv_kernel<<<dim3(H_ / 64, (B_ * T_ + 63) / 64, 4), 256>>>(
        ehs, idemb, Wk, Wv, Wid_k, Wid_v);

    // q = hs @ Wq  (HMMA bf16x3) -> bf16 splits
    gemm_hmma<0><<<dim3(GN / 128, ROWS / 128), 256, gemm_smem>>>(nullptr, nullptr);

    // flash attention (HMMA) -> bf16 splits
    attn_kernel<<<dim3(S_ / 128, B_ * NHEADS), 256, attn_smem>>>();

    // out = att @ Wout + bout  (HMMA bf16x3)
    gemm_hmma<1><<<dim3(GN / 128, ROWS / 128), 256, gemm_smem>>>(bout, out);
}

// round 10
// speedup vs baseline: 1.7239x; 1.2971x over previous
#include <cuda_runtime.h>
#include <cuda_fp16.h>
#include <cstdint>
#include <math.h>

// Problem constants
#define B_      4
#define S_      4096
#define H_      1280
#define C_      2048
#define T_      77
#define I_      32
#define NHEADS  20
#define DH      64
#define L_      (T_ + I_)       // 109
#define LPAD    112             // K rows padded (mult of 16)
#define LPAD2   120             // V^T row length (240B rows -> conflict-free)
#define ROWS    (B_ * S_)       // 16384

// ---------------------------------------------------------------------------
// Scratch (device globals; zero-initialized; no allocations allowed)
// fp16 2-product scheme: activations split hi/lo, weights/K/V single fp16.
// ---------------------------------------------------------------------------
__device__ __half g_q_hi[ROWS * H_];      // q projection, fp16 split
__device__ __half g_q_lo[ROWS * H_];
__device__ __half g_att_hi[ROWS * H_];    // attention out, fp16 split
__device__ __half g_att_lo[ROWS * H_];
__device__ __half g_hs_hi[ROWS * H_];     // hidden_states, fp16 split
__device__ __half g_hs_lo[ROWS * H_];
__device__ __half g_wq[H_ * H_];          // Wq^T [N,K], single fp16
__device__ __half g_wo[H_ * H_];          // Wout^T [N,K], single fp16
__device__ __half g_k[B_ * LPAD * H_];    // K [b][l][n], rows 109..111 zero
__device__ __half g_vt[B_ * H_ * LPAD2];  // V^T [b][n][l], l 109..119 zero

// ---------------------------------------------------------------------------
// PTX helpers (sm_100 base target — NO tcgen05, which needs the 'a' variant)
// ---------------------------------------------------------------------------
#define CP_ASYNC_16(dst, src) \
    asm volatile("cp.async.cg.shared.global [%0], [%1], 16;" :: "r"(dst), "l"(src) : "memory")
#define CP_COMMIT() asm volatile("cp.async.commit_group;" ::: "memory")
#define CP_WAIT1()  asm volatile("cp.async.wait_group 1;" ::: "memory")
#define CP_WAIT0()  asm volatile("cp.async.wait_group 0;" ::: "memory")

__device__ __forceinline__ uint32_t smem_to_u32(const void* p) {
    uint32_t a;
    asm("{ .reg .u64 t; cvta.to.shared.u64 t, %1; cvt.u32.u64 %0, t; }"
        : "=r"(a) : "l"(p));
    return a;
}

__device__ __forceinline__ void ldsm_x4(uint32_t& r0, uint32_t& r1,
                                        uint32_t& r2, uint32_t& r3, uint32_t addr) {
    asm volatile("ldmatrix.sync.aligned.m8n8.x4.shared.b16 {%0,%1,%2,%3}, [%4];"
                 : "=r"(r0), "=r"(r1), "=r"(r2), "=r"(r3) : "r"(addr));
}

__device__ __forceinline__ void mma_f16(float* d, const uint32_t* a,
                                        uint32_t b0, uint32_t b1) {
    asm volatile(
        "mma.sync.aligned.m16n8k16.row.col.f32.f16.f16.f32 "
        "{%0,%1,%2,%3}, {%4,%5,%6,%7}, {%8,%9}, {%0,%1,%2,%3};"
        : "+f"(d[0]), "+f"(d[1]), "+f"(d[2]), "+f"(d[3])
        : "r"(a[0]), "r"(a[1]), "r"(a[2]), "r"(a[3]), "r"(b0), "r"(b1));
}

__device__ __forceinline__ uint32_t h2_bits(__half2 v) {
    return *reinterpret_cast<uint32_t*>(&v);
}

// fp16 two-term split of fp32 (exact to ~2^-22)
__device__ __forceinline__ void f16split(float x, __half& h, __half& l) {
    h = __float2half_rn(x);
    l = __float2half_rn(x - __half2float(h));
}

// ---------------------------------------------------------------------------
// Prep 1: elementwise split of hidden_states -> g_hs_hi/lo
// ---------------------------------------------------------------------------
__global__ void __launch_bounds__(256) split_kernel(const float* __restrict__ src)
{
    size_t i = ((size_t)blockIdx.x * 256 + threadIdx.x) * 4;
    float4 v = *(const float4*)(src + i);
    __half h0, l0, h1, l1, h2, l2, h3, l3;
    f16split(v.x, h0, l0); f16split(v.y, h1, l1);
    f16split(v.z, h2, l2); f16split(v.w, h3, l3);
    *(__half2*)(g_hs_hi + i)     = __half2(h0, h1);
    *(__half2*)(g_hs_hi + i + 2) = __half2(h2, h3);
    *(__half2*)(g_hs_lo + i)     = __half2(l0, l1);
    *(__half2*)(g_hs_lo + i + 2) = __half2(l2, l3);
}

// ---------------------------------------------------------------------------
// Prep 2: transpose Wq and Wout -> [N, K] single fp16
// ---------------------------------------------------------------------------
__global__ void __launch_bounds__(256) tsplit_kernel(const float* __restrict__ Wq,
                                                     const float* __restrict__ Wout)
{
    __shared__ float t[32][33];
    const float* W = blockIdx.z ? Wout : Wq;
    __half* dh = blockIdx.z ? g_wo : g_wq;
    int bx = blockIdx.x * 32, by = blockIdx.y * 32;
    int tx = threadIdx.x, ty = threadIdx.y;
    #pragma unroll
    for (int i = 0; i < 4; i++)
        t[ty + 8 * i][tx] = W[(size_t)(by + ty + 8 * i) * H_ + bx + tx];
    __syncthreads();
    #pragma unroll
    for (int i = 0; i < 4; i++) {
        size_t o = (size_t)(bx + ty + 8 * i) * H_ + by + tx;   // [n][k]
        dh[o] = __float2half_rn(t[tx][ty + 8 * i]);
    }
}

// ---------------------------------------------------------------------------
// KV build: fp32 SIMT GEMM; K -> [b][LPAD][H_] fp16, V -> V^T [b][H_][LPAD2].
// ---------------------------------------------------------------------------
__device__ __forceinline__ void kv_store(bool is_v, int b, int l, int n,
                                         const float* vals)
{
    if (!is_v) {
        size_t a = ((size_t)b * LPAD + l) * H_ + n;
        *(__half2*)(g_k + a)     = __half2(__float2half_rn(vals[0]), __float2half_rn(vals[1]));
        *(__half2*)(g_k + a + 2) = __half2(__float2half_rn(vals[2]), __float2half_rn(vals[3]));
    } else {
        #pragma unroll
        for (int j = 0; j < 4; j++)
            g_vt[((size_t)b * H_ + n + j) * LPAD2 + l] = __float2half_rn(vals[j]);
    }
}

__global__ void __launch_bounds__(256) kv_kernel(
    const float* __restrict__ ehs, const float* __restrict__ idemb,
    const float* __restrict__ Wk, const float* __restrict__ Wv,
    const float* __restrict__ Wid_k, const float* __restrict__ Wid_v)
{
    const int z = blockIdx.z;
    const bool is_id = (z >= 2);
    const bool is_v  = (z & 1);
    const float* A = is_id ? idemb : ehs;
    const float* W = is_id ? (is_v ? Wid_v : Wid_k) : (is_v ? Wv : Wk);
    const int Mloc = is_id ? (2 * I_) : (B_ * T_);

    const int m0 = blockIdx.y * 64;
    if (m0 >= Mloc) return;
    const int n0 = blockIdx.x * 64;

    __shared__ float As[16][68];
    __shared__ float Bs[16][64];

    const int tid  = threadIdx.x;
    const int arow = tid >> 2;
    const int ac4  = (tid & 3) * 4;
    const int brow = tid >> 4;
    const int bc4  = (tid & 15) * 4;
    const int tx   = tid & 15;
    const int ty   = tid >> 4;

    float acc[4][4];
    #pragma unroll
    for (int i = 0; i < 4; i++)
        #pragma unroll
        for (int j = 0; j < 4; j++) acc[i][j] = 0.f;

    for (int k0 = 0; k0 < C_; k0 += 16) {
        float4 av = make_float4(0.f, 0.f, 0.f, 0.f);
        if (m0 + arow < Mloc)
            av = *(const float4*)(A + (size_t)(m0 + arow) * C_ + k0 + ac4);
        float4 bv = *(const float4*)(W + (size_t)(k0 + brow) * H_ + n0 + bc4);
        __syncthreads();
        As[ac4 + 0][arow] = av.x;
        As[ac4 + 1][arow] = av.y;
        As[ac4 + 2][arow] = av.z;
        As[ac4 + 3][arow] = av.w;
        *(float4*)&Bs[brow][bc4] = bv;
        __syncthreads();
        #pragma unroll
        for (int kk = 0; kk < 16; kk++) {
            float4 a = *(const float4*)&As[kk][ty * 4];
            float4 b = *(const float4*)&Bs[kk][tx * 4];
            float am[4] = {a.x, a.y, a.z, a.w};
            float bn[4] = {b.x, b.y, b.z, b.w};
            #pragma unroll
            for (int i = 0; i < 4; i++)
                #pragma unroll
                for (int j = 0; j < 4; j++)
                    acc[i][j] += am[i] * bn[j];
        }
    }

    #pragma unroll
    for (int i = 0; i < 4; i++) {
        int r = m0 + ty * 4 + i;
        if (r >= Mloc) continue;
        if (!is_id) {
            int batch = r / T_, pos = r % T_;
            kv_store(is_v, batch, pos, n0 + tx * 4, acc[i]);
        } else {
            int hb = r >> 5, ii = r & 31;
            kv_store(is_v, hb,     T_ + ii, n0 + tx * 4, acc[i]);
            kv_store(is_v, hb + 2, T_ + ii, n0 + tx * 4, acc[i]);
        }
    }
}

// ---------------------------------------------------------------------------
// HMMA fp16x2 GEMM: C = A @ B^T. A = activation splits (hi/lo fp16),
// B = single fp16 weights. 2 MMA products per tile (was 3 with bf16x3).
// CTA 128x128, BK=32, 8 warps (4x2), warp tile 32x64, 2 CTAs/SM, 3 stages,
// R6 ordering (MMA first, refill after).
// MODE 0: A=g_hs B=g_wq -> fp16 splits to g_q_hi/lo
// MODE 1: A=g_att B=g_wo -> fp32 + bias to Cp
// ---------------------------------------------------------------------------
#define GK       H_          // 1280
#define GN       H_          // 1280
#define BK       32
#define NIT      (GK / BK)   // 40
#define TILE_B   (128 * 64)  // 8192 B
#define STAGE_B  (3 * TILE_B)   // Ah, Al, B = 24576 B
#define NSTAGE   3

__device__ __forceinline__ uint32_t swz(int row, int chunk) {
    return (uint32_t)(row * 64 + ((chunk ^ ((row >> 1) & 3)) << 4));
}

__device__ __forceinline__ void fill_tile(uint32_t dst, const __half* src,
                                          int k0, int tid)
{
    #pragma unroll
    for (int i = 0; i < 2; i++) {
        int idx = i * 256 + tid;
        int row = idx >> 2;
        int c   = idx & 3;
        CP_ASYNC_16(dst + swz(row, c),
                    src + (size_t)row * GK + k0 + c * 8);
    }
}

template<int MODE>
__global__ void __launch_bounds__(256, 2) gemm_hmma(
    const float* __restrict__ bias, float* __restrict__ Cp)
{
    const __half* Ahi = (MODE == 0) ? g_hs_hi : g_att_hi;
    const __half* Alo = (MODE == 0) ? g_hs_lo : g_att_lo;
    const __half* Bw  = (MODE == 0) ? g_wq : g_wo;

    extern __shared__ char smem[];
    const uint32_t sb = smem_to_u32(smem);

    const int tid  = threadIdx.x;
    const int wid  = tid >> 5;
    const int lane = tid & 31;
    const int wm   = wid >> 1;
    const int wn   = wid & 1;
    const int n0 = blockIdx.x * 128;
    const int m0 = blockIdx.y * 128;

    const __half* aH = Ahi + (size_t)m0 * GK;
    const __half* aL = Alo + (size_t)m0 * GK;
    const __half* bW = Bw  + (size_t)n0 * GK;

    const int a_row_off = (lane & 7) + ((lane >> 3) & 1) * 8;
    const int a_half    = lane >> 4;
    const int b_row_off = (lane & 7) + ((lane >> 4) & 1) * 8;
    const int b_half    = (lane >> 3) & 1;

    float acc[2][8][4];
    #pragma unroll
    for (int mt = 0; mt < 2; mt++)
        #pragma unroll
        for (int nt = 0; nt < 8; nt++)
            #pragma unroll
            for (int c = 0; c < 4; c++) acc[mt][nt][c] = 0.f;

    #pragma unroll
    for (int st = 0; st < 2; st++) {
        uint32_t s = sb + st * STAGE_B;
        fill_tile(s + 0 * TILE_B, aH, st * BK, tid);
        fill_tile(s + 1 * TILE_B, aL, st * BK, tid);
        fill_tile(s + 2 * TILE_B, bW, st * BK, tid);
        CP_COMMIT();
    }

    int stage = 0;
    for (int it = 0; it < NIT; it++) {
        uint32_t s = sb + stage * STAGE_B;
        CP_WAIT1();
        __syncthreads();

        const uint32_t sAh = s + 0 * TILE_B;
        const uint32_t sAl = s + 1 * TILE_B;
        const uint32_t sBw = s + 2 * TILE_B;

        #pragma unroll
        for (int ks = 0; ks < 2; ks++) {
            uint32_t fAh[2][4], fAl[2][4];
            #pragma unroll
            for (int mt = 0; mt < 2; mt++) {
                int row = wm * 32 + mt * 16 + a_row_off;
                uint32_t ad = swz(row, ks * 2 + a_half);
                ldsm_x4(fAh[mt][0], fAh[mt][1], fAh[mt][2], fAh[mt][3], sAh + ad);
                ldsm_x4(fAl[mt][0], fAl[mt][1], fAl[mt][2], fAl[mt][3], sAl + ad);
            }
            #pragma unroll
            for (int g = 0; g < 4; g++) {
                int row = wn * 64 + g * 16 + b_row_off;
                uint32_t bd = swz(row, ks * 2 + b_half);
                uint32_t b0, b1, b2, b3;
                ldsm_x4(b0, b1, b2, b3, sBw + bd);
                #pragma unroll
                for (int mt = 0; mt < 2; mt++) {
                    mma_f16(acc[mt][g * 2 + 0], fAh[mt], b0, b1);
                    mma_f16(acc[mt][g * 2 + 1], fAh[mt], b2, b3);
                    mma_f16(acc[mt][g * 2 + 0], fAl[mt], b0, b1);
                    mma_f16(acc[mt][g * 2 + 1], fAl[mt], b2, b3);
                }
            }
        }

        if (it + 2 < NIT) {
            int fs = stage + 2 >= NSTAGE ? stage + 2 - NSTAGE : stage + 2;
            uint32_t f = sb + fs * STAGE_B;
            int k0 = (it + 2) * BK;
            fill_tile(f + 0 * TILE_B, aH, k0, tid);
            fill_tile(f + 1 * TILE_B, aL, k0, tid);
            fill_tile(f + 2 * TILE_B, bW, k0, tid);
        }
        CP_COMMIT();
        stage = stage + 1 >= NSTAGE ? 0 : stage + 1;
    }

    // Epilogue
    const int gid = lane >> 2, tig = lane & 3;
    #pragma unroll
    for (int mt = 0; mt < 2; mt++) {
        #pragma unroll
        for (int nt = 0; nt < 8; nt++) {
            int r   = m0 + wm * 32 + mt * 16 + gid;
            int col = n0 + wn * 64 + nt * 8 + tig * 2;
            if (MODE == 0) {
                #pragma unroll
                for (int half = 0; half < 2; half++) {
                    int rr = r + half * 8;
                    __half h0, l0, h1, l1;
                    f16split(acc[mt][nt][half * 2 + 0], h0, l0);
                    f16split(acc[mt][nt][half * 2 + 1], h1, l1);
                    size_t a = (size_t)rr * GN + col;
                    *(__half2*)(g_q_hi + a) = __half2(h0, h1);
                    *(__half2*)(g_q_lo + a) = __half2(l0, l1);
                }
            } else {
                float b0v = bias[col], b1v = bias[col + 1];
                float2 v0 = make_float2(acc[mt][nt][0] + b0v, acc[mt][nt][1] + b1v);
                float2 v1 = make_float2(acc[mt][nt][2] + b0v, acc[mt][nt][3] + b1v);
                *(float2*)(Cp + (size_t)r * GN + col)       = v0;
                *(float2*)(Cp + (size_t)(r + 8) * GN + col) = v1;
            }
        }
    }
}

// ---------------------------------------------------------------------------
// HMMA flash attention (fp16x2). CTA = 128 queries x one (b,h). 8 warps.
// QK: A = q splits, B = K single fp16 -> 2 products.
// PV: A = p splits (C->A repack), B = V^T single fp16 -> 2 products.
// Smem: Qh/Ql 128x128B swz | K 112x128B swz | V 64x240B natural.
// ---------------------------------------------------------------------------
#define ASM_Q   0
#define ASM_K   (2 * 128 * 128)                 // 32768
#define ASM_V   (ASM_K + LPAD * 128)            // 32768 + 14336 = 47104
#define ASM_TOT (ASM_V + 64 * 240)              // 47104 + 15360 = 62464

__device__ __forceinline__ uint32_t swz128(int row, int chunk) {
    return (uint32_t)(row * 128 + ((chunk ^ (row & 7)) << 4));
}

__global__ void __launch_bounds__(256, 2) attn_kernel()
{
    extern __shared__ char asmem[];
    const uint32_t sb = smem_to_u32(asmem);
    const uint32_t sQh = sb + ASM_Q,  sQl = sQh + 128 * 128;
    const uint32_t sK  = sb + ASM_K;
    const uint32_t sV  = sb + ASM_V;

    const int tid  = threadIdx.x;
    const int wid  = tid >> 5;
    const int lane = tid & 31;
    const int bh = blockIdx.y;
    const int batch = bh / NHEADS;
    const int h = bh % NHEADS;
    const int qrow0 = batch * S_ + blockIdx.x * 128;

    // ---- loads (one-shot, cp.async) ----
    {
        const __half* qh = g_q_hi + (size_t)qrow0 * H_ + h * DH;
        const __half* ql = g_q_lo + (size_t)qrow0 * H_ + h * DH;
        #pragma unroll
        for (int i = 0; i < 4; i++) {
            int idx = i * 256 + tid;            // 0..1023
            int row = idx >> 3, c = idx & 7;
            CP_ASYNC_16(sQh + swz128(row, c), qh + (size_t)row * H_ + c * 8);
            CP_ASYNC_16(sQl + swz128(row, c), ql + (size_t)row * H_ + c * 8);
        }
        const __half* kp = g_k + (size_t)batch * LPAD * H_ + h * DH;
        for (int idx = tid; idx < LPAD * 8; idx += 256) {
            int row = idx >> 3, c = idx & 7;
            CP_ASYNC_16(sK + swz128(row, c), kp + (size_t)row * H_ + c * 8);
        }
        const __half* vp = g_vt + ((size_t)batch * H_ + h * DH) * LPAD2;
        for (int idx = tid; idx < 64 * 14; idx += 256) {
            int row = idx / 14, c = idx % 14;
            CP_ASYNC_16(sV + (uint32_t)(row * 240 + c * 16),
                        vp + (size_t)row * LPAD2 + c * 8);
        }
        CP_COMMIT();
    }
    CP_WAIT0();
    __syncthreads();

    const int gid = lane >> 2, tig = lane & 3;
    const int a_row_off = (lane & 7) + ((lane >> 3) & 1) * 8;
    const int a_half    = lane >> 4;
    const int b_row_off = (lane & 7) + ((lane >> 4) & 1) * 8;
    const int b_half    = (lane >> 3) & 1;

    // q fragments (held across the l-loop): 4 k-steps x hi/lo
    uint32_t fQh[4][4], fQl[4][4];
    #pragma unroll
    for (int ks = 0; ks < 4; ks++) {
        int row = wid * 16 + a_row_off;
        uint32_t ad = swz128(row, ks * 2 + a_half);
        ldsm_x4(fQh[ks][0], fQh[ks][1], fQh[ks][2], fQh[ks][3], sQh + ad);
        ldsm_x4(fQl[ks][0], fQl[ks][1], fQl[ks][2], fQl[ks][3], sQl + ad);
    }

    float acc[8][4];
    #pragma unroll
    for (int nt = 0; nt < 8; nt++)
        #pragma unroll
        for (int c = 0; c < 4; c++) acc[nt][c] = 0.f;
    float rs0 = 0.f, rs1 = 0.f;
    const float scale = 0.125f;

    #pragma unroll
    for (int kt = 0; kt < 7; kt++) {       // l tiles of 16 (0..111)
        // --- QK scores for n-tiles 2kt, 2kt+1 ---
        float c0[4] = {0.f, 0.f, 0.f, 0.f};
        float c1[4] = {0.f, 0.f, 0.f, 0.f};
        #pragma unroll
        for (int ks = 0; ks < 4; ks++) {
            int row = kt * 16 + b_row_off;
            uint32_t bd = swz128(row, ks * 2 + b_half);
            uint32_t kb0, kb1, kb2, kb3;
            ldsm_x4(kb0, kb1, kb2, kb3, sK + bd);
            mma_f16(c0, fQh[ks], kb0, kb1);
            mma_f16(c1, fQh[ks], kb2, kb3);
            mma_f16(c0, fQl[ks], kb0, kb1);
            mma_f16(c1, fQl[ks], kb2, kb3);
        }
        // --- exp + mask + row sums ---
        float e0[4], e1[4];
        #pragma unroll
        for (int j = 0; j < 4; j++) {
            e0[j] = __expf(c0[j] * scale);
            e1[j] = __expf(c1[j] * scale);
        }
        if (kt == 6) {   // n-tile 13: cols 104..111, mask col >= 109
            float m0v = (104 + 2 * tig <= 108) ? 1.f : 0.f;
            float m1v = (105 + 2 * tig <= 108) ? 1.f : 0.f;
            e1[0] *= m0v; e1[1] *= m1v; e1[2] *= m0v; e1[3] *= m1v;
        }
        rs0 += e0[0] + e0[1] + e1[0] + e1[1];
        rs1 += e0[2] + e0[3] + e1[2] + e1[3];
        // --- p fragments (FA2 C->A repack) + fp16 lo split ---
        uint32_t ah[4], al[4];
        float ev[8] = {e0[0], e0[1], e0[2], e0[3], e1[0], e1[1], e1[2], e1[3]};
        #pragma unroll
        for (int j = 0; j < 4; j++) {
            __half2 hh = __floats2half2_rn(ev[2 * j], ev[2 * j + 1]);
            ah[j] = h2_bits(hh);
            __half2 ll = __floats2half2_rn(ev[2 * j]     - __half2float(hh.x),
                                           ev[2 * j + 1] - __half2float(hh.y));
            al[j] = h2_bits(ll);
        }
        // --- PV: acc += p @ V^T-tile (k16 = these 16 l's) ---
        #pragma unroll
        for (int g = 0; g < 4; g++) {
            uint32_t bd = (uint32_t)((g * 16 + b_row_off) * 240 +
                                     (kt * 2 + b_half) * 16);
            uint32_t vb0, vb1, vb2, vb3;
            ldsm_x4(vb0, vb1, vb2, vb3, sV + bd);
            mma_f16(acc[g * 2 + 0], ah, vb0, vb1);
            mma_f16(acc[g * 2 + 1], ah, vb2, vb3);
            mma_f16(acc[g * 2 + 0], al, vb0, vb1);
            mma_f16(acc[g * 2 + 1], al, vb2, vb3);
        }
    }

    // quad reduction of row sums
    rs0 += __shfl_xor_sync(0xffffffffu, rs0, 1);
    rs0 += __shfl_xor_sync(0xffffffffu, rs0, 2);
    rs1 += __shfl_xor_sync(0xffffffffu, rs1, 1);
    rs1 += __shfl_xor_sync(0xffffffffu, rs1, 2);
    const float inv0 = 1.f / rs0;
    const float inv1 = 1.f / rs1;

    // epilogue: normalize, split, store to g_att_hi/lo
    const int r0 = qrow0 + wid * 16 + gid;
    #pragma unroll
    for (int nt = 0; nt < 8; nt++) {
        int col = h * DH + nt * 8 + tig * 2;
        __half h0, l0, h1, l1;
        f16split(acc[nt][0] * inv0, h0, l0);
        f16split(acc[nt][1] * inv0, h1, l1);
        size_t a = (size_t)r0 * H_ + col;
        *(__half2*)(g_att_hi + a) = __half2(h0, h1);
        *(__half2*)(g_att_lo + a) = __half2(l0, l1);
        f16split(acc[nt][2] * inv1, h0, l0);
        f16split(acc[nt][3] * inv1, h1, l1);
        a = (size_t)(r0 + 8) * H_ + col;
        *(__half2*)(g_att_hi + a) = __half2(h0, h1);
        *(__half2*)(g_att_lo + a) = __half2(l0, l1);
    }
}

// ---------------------------------------------------------------------------
extern "C" void kernel_launch(void* const* d_in, const int* in_sizes, int n_in,
                              void* d_out, int out_size)
{
    (void)in_sizes; (void)n_in; (void)out_size;
    const float* hs    = (const float*)d_in[0];
    const float* ehs   = (const float*)d_in[1];
    const float* idemb = (const float*)d_in[2];
    const float* Wq    = (const float*)d_in[3];
    const float* Wk    = (const float*)d_in[4];
    const float* Wv    = (const float*)d_in[5];
    const float* Wid_k = (const float*)d_in[6];
    const float* Wid_v = (const float*)d_in[7];
    const float* Wout  = (const float*)d_in[8];
    const float* bout  = (const float*)d_in[9];
    float* out = (float*)d_out;

    const int attn_smem = ASM_TOT;            // 62,464 B
    const int gemm_smem = NSTAGE * STAGE_B;   // 73,728 B
    cudaFuncSetAttribute(attn_kernel,
                         cudaFuncAttributeMaxDynamicSharedMemorySize, attn_smem);
    cudaFuncSetAttribute(gemm_hmma<0>,
                         cudaFuncAttributeMaxDynamicSharedMemorySize, gemm_smem);
    cudaFuncSetAttribute(gemm_hmma<1>,
                         cudaFuncAttributeMaxDynamicSharedMemorySize, gemm_smem);

    // Prep: fp16 splits / fp16 weights
    split_kernel<<<(ROWS * H_ / 4 + 255) / 256, 256>>>(hs);
    tsplit_kernel<<<dim3(H_ / 32, H_ / 32, 2), dim3(32, 8)>>>(Wq, Wout);

    // K/V projections -> fp16 (K row-major, V transposed)
    kv_kernel<<<dim3(H_ / 64, (B_ * T_ + 63) / 64, 4), 256>>>(
        ehs, idemb, Wk, Wv, Wid_k, Wid_v);

    // q = hs @ Wq  (HMMA fp16x2) -> fp16 splits
    gemm_hmma<0><<<dim3(GN / 128, ROWS / 128), 256, gemm_smem>>>(nullptr, nullptr);

    // flash attention (HMMA fp16x2) -> fp16 splits
    attn_kernel<<<dim3(S_ / 128, B_ * NHEADS), 256, attn_smem>>>();

    // out = att @ Wout + bout  (HMMA fp16x2)
    gemm_hmma<1><<<dim3(GN / 128, ROWS / 128), 256, gemm_smem>>>(bout, out);
}

// round 11
// speedup vs baseline: 1.9290x; 1.1190x over previous
#include <cuda_runtime.h>
#include <cuda_fp16.h>
#include <cstdint>
#include <math.h>

// Problem constants
#define B_      4
#define S_      4096
#define H_      1280
#define C_      2048
#define T_      77
#define I_      32
#define NHEADS  20
#define DH      64
#define L_      (T_ + I_)       // 109
#define LPAD    112             // K rows padded (mult of 16)
#define LPAD2   120             // V^T row length (240B rows -> conflict-free)
#define ROWS    (B_ * S_)       // 16384

// ---------------------------------------------------------------------------
// Scratch (device globals; zero-initialized; no allocations allowed)
// fp16 2-product scheme: activations split hi/lo, weights/K/V single fp16.
// ---------------------------------------------------------------------------
__device__ __half g_q_hi[ROWS * H_];      // q projection, fp16 split
__device__ __half g_q_lo[ROWS * H_];
__device__ __half g_att_hi[ROWS * H_];    // attention out, fp16 split
__device__ __half g_att_lo[ROWS * H_];
__device__ __half g_hs_hi[ROWS * H_];     // hidden_states, fp16 split
__device__ __half g_hs_lo[ROWS * H_];
__device__ __half g_wq[H_ * H_];          // Wq^T [N,K], single fp16
__device__ __half g_wo[H_ * H_];          // Wout^T [N,K], single fp16
__device__ __half g_k[B_ * LPAD * H_];    // K [b][l][n], rows 109..111 zero
__device__ __half g_vt[B_ * H_ * LPAD2];  // V^T [b][n][l], l 109..119 zero

// ---------------------------------------------------------------------------
// PTX helpers (sm_100 base target — NO tcgen05, which needs the 'a' variant)
// ---------------------------------------------------------------------------
#define CP_ASYNC_16(dst, src) \
    asm volatile("cp.async.cg.shared.global [%0], [%1], 16;" :: "r"(dst), "l"(src) : "memory")
#define CP_COMMIT() asm volatile("cp.async.commit_group;" ::: "memory")
#define CP_WAIT2()  asm volatile("cp.async.wait_group 2;" ::: "memory")
#define CP_WAIT0()  asm volatile("cp.async.wait_group 0;" ::: "memory")

__device__ __forceinline__ uint32_t smem_to_u32(const void* p) {
    uint32_t a;
    asm("{ .reg .u64 t; cvta.to.shared.u64 t, %1; cvt.u32.u64 %0, t; }"
        : "=r"(a) : "l"(p));
    return a;
}

__device__ __forceinline__ void ldsm_x4(uint32_t& r0, uint32_t& r1,
                                        uint32_t& r2, uint32_t& r3, uint32_t addr) {
    asm volatile("ldmatrix.sync.aligned.m8n8.x4.shared.b16 {%0,%1,%2,%3}, [%4];"
                 : "=r"(r0), "=r"(r1), "=r"(r2), "=r"(r3) : "r"(addr));
}

__device__ __forceinline__ void mma_f16(float* d, const uint32_t* a,
                                        uint32_t b0, uint32_t b1) {
    asm volatile(
        "mma.sync.aligned.m16n8k16.row.col.f32.f16.f16.f32 "
        "{%0,%1,%2,%3}, {%4,%5,%6,%7}, {%8,%9}, {%0,%1,%2,%3};"
        : "+f"(d[0]), "+f"(d[1]), "+f"(d[2]), "+f"(d[3])
        : "r"(a[0]), "r"(a[1]), "r"(a[2]), "r"(a[3]), "r"(b0), "r"(b1));
}

__device__ __forceinline__ uint32_t h2_bits(__half2 v) {
    return *reinterpret_cast<uint32_t*>(&v);
}

// fp16 two-term split of fp32 (exact to ~2^-22)
__device__ __forceinline__ void f16split(float x, __half& h, __half& l) {
    h = __float2half_rn(x);
    l = __float2half_rn(x - __half2float(h));
}

// ---------------------------------------------------------------------------
// Prep 1: elementwise split of hidden_states -> g_hs_hi/lo
// ---------------------------------------------------------------------------
__global__ void __launch_bounds__(256) split_kernel(const float* __restrict__ src)
{
    size_t i = ((size_t)blockIdx.x * 256 + threadIdx.x) * 4;
    float4 v = *(const float4*)(src + i);
    __half h0, l0, h1, l1, h2, l2, h3, l3;
    f16split(v.x, h0, l0); f16split(v.y, h1, l1);
    f16split(v.z, h2, l2); f16split(v.w, h3, l3);
    *(__half2*)(g_hs_hi + i)     = __half2(h0, h1);
    *(__half2*)(g_hs_hi + i + 2) = __half2(h2, h3);
    *(__half2*)(g_hs_lo + i)     = __half2(l0, l1);
    *(__half2*)(g_hs_lo + i + 2) = __half2(l2, l3);
}

// ---------------------------------------------------------------------------
// Prep 2: transpose Wq and Wout -> [N, K] single fp16
// ---------------------------------------------------------------------------
__global__ void __launch_bounds__(256) tsplit_kernel(const float* __restrict__ Wq,
                                                     const float* __restrict__ Wout)
{
    __shared__ float t[32][33];
    const float* W = blockIdx.z ? Wout : Wq;
    __half* dh = blockIdx.z ? g_wo : g_wq;
    int bx = blockIdx.x * 32, by = blockIdx.y * 32;
    int tx = threadIdx.x, ty = threadIdx.y;
    #pragma unroll
    for (int i = 0; i < 4; i++)
        t[ty + 8 * i][tx] = W[(size_t)(by + ty + 8 * i) * H_ + bx + tx];
    __syncthreads();
    #pragma unroll
    for (int i = 0; i < 4; i++) {
        size_t o = (size_t)(bx + ty + 8 * i) * H_ + by + tx;   // [n][k]
        dh[o] = __float2half_rn(t[tx][ty + 8 * i]);
    }
}

// ---------------------------------------------------------------------------
// KV build: fp32 SIMT GEMM; K -> [b][LPAD][H_] fp16, V -> V^T [b][H_][LPAD2].
// ---------------------------------------------------------------------------
__device__ __forceinline__ void kv_store(bool is_v, int b, int l, int n,
                                         const float* vals)
{
    if (!is_v) {
        size_t a = ((size_t)b * LPAD + l) * H_ + n;
        *(__half2*)(g_k + a)     = __half2(__float2half_rn(vals[0]), __float2half_rn(vals[1]));
        *(__half2*)(g_k + a + 2) = __half2(__float2half_rn(vals[2]), __float2half_rn(vals[3]));
    } else {
        #pragma unroll
        for (int j = 0; j < 4; j++)
            g_vt[((size_t)b * H_ + n + j) * LPAD2 + l] = __float2half_rn(vals[j]);
    }
}

__global__ void __launch_bounds__(256) kv_kernel(
    const float* __restrict__ ehs, const float* __restrict__ idemb,
    const float* __restrict__ Wk, const float* __restrict__ Wv,
    const float* __restrict__ Wid_k, const float* __restrict__ Wid_v)
{
    const int z = blockIdx.z;
    const bool is_id = (z >= 2);
    const bool is_v  = (z & 1);
    const float* A = is_id ? idemb : ehs;
    const float* W = is_id ? (is_v ? Wid_v : Wid_k) : (is_v ? Wv : Wk);
    const int Mloc = is_id ? (2 * I_) : (B_ * T_);

    const int m0 = blockIdx.y * 64;
    if (m0 >= Mloc) return;
    const int n0 = blockIdx.x * 64;

    __shared__ float As[16][68];
    __shared__ float Bs[16][64];

    const int tid  = threadIdx.x;
    const int arow = tid >> 2;
    const int ac4  = (tid & 3) * 4;
    const int brow = tid >> 4;
    const int bc4  = (tid & 15) * 4;
    const int tx   = tid & 15;
    const int ty   = tid >> 4;

    float acc[4][4];
    #pragma unroll
    for (int i = 0; i < 4; i++)
        #pragma unroll
        for (int j = 0; j < 4; j++) acc[i][j] = 0.f;

    for (int k0 = 0; k0 < C_; k0 += 16) {
        float4 av = make_float4(0.f, 0.f, 0.f, 0.f);
        if (m0 + arow < Mloc)
            av = *(const float4*)(A + (size_t)(m0 + arow) * C_ + k0 + ac4);
        float4 bv = *(const float4*)(W + (size_t)(k0 + brow) * H_ + n0 + bc4);
        __syncthreads();
        As[ac4 + 0][arow] = av.x;
        As[ac4 + 1][arow] = av.y;
        As[ac4 + 2][arow] = av.z;
        As[ac4 + 3][arow] = av.w;
        *(float4*)&Bs[brow][bc4] = bv;
        __syncthreads();
        #pragma unroll
        for (int kk = 0; kk < 16; kk++) {
            float4 a = *(const float4*)&As[kk][ty * 4];
            float4 b = *(const float4*)&Bs[kk][tx * 4];
            float am[4] = {a.x, a.y, a.z, a.w};
            float bn[4] = {b.x, b.y, b.z, b.w};
            #pragma unroll
            for (int i = 0; i < 4; i++)
                #pragma unroll
                for (int j = 0; j < 4; j++)
                    acc[i][j] += am[i] * bn[j];
        }
    }

    #pragma unroll
    for (int i = 0; i < 4; i++) {
        int r = m0 + ty * 4 + i;
        if (r >= Mloc) continue;
        if (!is_id) {
            int batch = r / T_, pos = r % T_;
            kv_store(is_v, batch, pos, n0 + tx * 4, acc[i]);
        } else {
            int hb = r >> 5, ii = r & 31;
            kv_store(is_v, hb,     T_ + ii, n0 + tx * 4, acc[i]);
            kv_store(is_v, hb + 2, T_ + ii, n0 + tx * 4, acc[i]);
        }
    }
}

// ---------------------------------------------------------------------------
// HMMA fp16x2 GEMM: C = A @ B^T. A = activation splits (hi/lo fp16),
// B = single fp16 weights. CTA 128x128, BK=32, 8 warps (4x2), warp tile
// 32x64, 2 CTAs/SM. R11: 4-stage cp.async pipeline (wait_group 2) — each
// load gets TWO MMA iterations of slack. R6 ordering (MMA first, refill after).
// MODE 0: A=g_hs B=g_wq -> fp16 splits to g_q_hi/lo
// MODE 1: A=g_att B=g_wo -> fp32 + bias to Cp
// ---------------------------------------------------------------------------
#define GK       H_          // 1280
#define GN       H_          // 1280
#define BK       32
#define NIT      (GK / BK)   // 40
#define TILE_B   (128 * 64)  // 8192 B
#define STAGE_B  (3 * TILE_B)   // Ah, Al, B = 24576 B
#define NSTAGE   4

__device__ __forceinline__ uint32_t swz(int row, int chunk) {
    return (uint32_t)(row * 64 + ((chunk ^ ((row >> 1) & 3)) << 4));
}

__device__ __forceinline__ void fill_tile(uint32_t dst, const __half* src,
                                          int k0, int tid)
{
    #pragma unroll
    for (int i = 0; i < 2; i++) {
        int idx = i * 256 + tid;
        int row = idx >> 2;
        int c   = idx & 3;
        CP_ASYNC_16(dst + swz(row, c),
                    src + (size_t)row * GK + k0 + c * 8);
    }
}

template<int MODE>
__global__ void __launch_bounds__(256, 2) gemm_hmma(
    const float* __restrict__ bias, float* __restrict__ Cp)
{
    const __half* Ahi = (MODE == 0) ? g_hs_hi : g_att_hi;
    const __half* Alo = (MODE == 0) ? g_hs_lo : g_att_lo;
    const __half* Bw  = (MODE == 0) ? g_wq : g_wo;

    extern __shared__ char smem[];
    const uint32_t sb = smem_to_u32(smem);

    const int tid  = threadIdx.x;
    const int wid  = tid >> 5;
    const int lane = tid & 31;
    const int wm   = wid >> 1;
    const int wn   = wid & 1;
    const int n0 = blockIdx.x * 128;
    const int m0 = blockIdx.y * 128;

    const __half* aH = Ahi + (size_t)m0 * GK;
    const __half* aL = Alo + (size_t)m0 * GK;
    const __half* bW = Bw  + (size_t)n0 * GK;

    const int a_row_off = (lane & 7) + ((lane >> 3) & 1) * 8;
    const int a_half    = lane >> 4;
    const int b_row_off = (lane & 7) + ((lane >> 4) & 1) * 8;
    const int b_half    = (lane >> 3) & 1;

    float acc[2][8][4];
    #pragma unroll
    for (int mt = 0; mt < 2; mt++)
        #pragma unroll
        for (int nt = 0; nt < 8; nt++)
            #pragma unroll
            for (int c = 0; c < 4; c++) acc[mt][nt][c] = 0.f;

    // Prologue: fill stages 0..2
    #pragma unroll
    for (int st = 0; st < NSTAGE - 1; st++) {
        uint32_t s = sb + st * STAGE_B;
        fill_tile(s + 0 * TILE_B, aH, st * BK, tid);
        fill_tile(s + 1 * TILE_B, aL, st * BK, tid);
        fill_tile(s + 2 * TILE_B, bW, st * BK, tid);
        CP_COMMIT();
    }

    int stage = 0;
    for (int it = 0; it < NIT; it++) {
        uint32_t s = sb + stage * STAGE_B;
        CP_WAIT2();
        __syncthreads();    // all warps done with stage refilled this iter

        const uint32_t sAh = s + 0 * TILE_B;
        const uint32_t sAl = s + 1 * TILE_B;
        const uint32_t sBw = s + 2 * TILE_B;

        #pragma unroll
        for (int ks = 0; ks < 2; ks++) {
            uint32_t fAh[2][4], fAl[2][4];
            #pragma unroll
            for (int mt = 0; mt < 2; mt++) {
                int row = wm * 32 + mt * 16 + a_row_off;
                uint32_t ad = swz(row, ks * 2 + a_half);
                ldsm_x4(fAh[mt][0], fAh[mt][1], fAh[mt][2], fAh[mt][3], sAh + ad);
                ldsm_x4(fAl[mt][0], fAl[mt][1], fAl[mt][2], fAl[mt][3], sAl + ad);
            }
            #pragma unroll
            for (int g = 0; g < 4; g++) {
                int row = wn * 64 + g * 16 + b_row_off;
                uint32_t bd = swz(row, ks * 2 + b_half);
                uint32_t b0, b1, b2, b3;
                ldsm_x4(b0, b1, b2, b3, sBw + bd);
                #pragma unroll
                for (int mt = 0; mt < 2; mt++) {
                    mma_f16(acc[mt][g * 2 + 0], fAh[mt], b0, b1);
                    mma_f16(acc[mt][g * 2 + 1], fAh[mt], b2, b3);
                    mma_f16(acc[mt][g * 2 + 0], fAl[mt], b0, b1);
                    mma_f16(acc[mt][g * 2 + 1], fAl[mt], b2, b3);
                }
            }
        }

        // Refill stage (it+3)%4 (consumed at it-1) with k-chunk it+3
        if (it + NSTAGE - 1 < NIT) {
            int fs = stage + NSTAGE - 1;
            if (fs >= NSTAGE) fs -= NSTAGE;
            uint32_t f = sb + fs * STAGE_B;
            int k0 = (it + NSTAGE - 1) * BK;
            fill_tile(f + 0 * TILE_B, aH, k0, tid);
            fill_tile(f + 1 * TILE_B, aL, k0, tid);
            fill_tile(f + 2 * TILE_B, bW, k0, tid);
        }
        CP_COMMIT();
        stage = stage + 1 >= NSTAGE ? 0 : stage + 1;
    }

    // Epilogue
    const int gid = lane >> 2, tig = lane & 3;
    #pragma unroll
    for (int mt = 0; mt < 2; mt++) {
        #pragma unroll
        for (int nt = 0; nt < 8; nt++) {
            int r   = m0 + wm * 32 + mt * 16 + gid;
            int col = n0 + wn * 64 + nt * 8 + tig * 2;
            if (MODE == 0) {
                #pragma unroll
                for (int half = 0; half < 2; half++) {
                    int rr = r + half * 8;
                    __half h0, l0, h1, l1;
                    f16split(acc[mt][nt][half * 2 + 0], h0, l0);
                    f16split(acc[mt][nt][half * 2 + 1], h1, l1);
                    size_t a = (size_t)rr * GN + col;
                    *(__half2*)(g_q_hi + a) = __half2(h0, h1);
                    *(__half2*)(g_q_lo + a) = __half2(l0, l1);
                }
            } else {
                float b0v = bias[col], b1v = bias[col + 1];
                float2 v0 = make_float2(acc[mt][nt][0] + b0v, acc[mt][nt][1] + b1v);
                float2 v1 = make_float2(acc[mt][nt][2] + b0v, acc[mt][nt][3] + b1v);
                *(float2*)(Cp + (size_t)r * GN + col)       = v0;
                *(float2*)(Cp + (size_t)(r + 8) * GN + col) = v1;
            }
        }
    }
}

// ---------------------------------------------------------------------------
// HMMA flash attention (fp16x2). CTA = 128 queries x one (b,h). 8 warps.
// QK: A = q splits, B = K single fp16 -> 2 products.
// PV: A = p splits (C->A repack), B = V^T single fp16 -> 2 products.
// Smem: Qh/Ql 128x128B swz | K 112x128B swz | V 64x240B natural.
// ---------------------------------------------------------------------------
#define ASM_Q   0
#define ASM_K   (2 * 128 * 128)                 // 32768
#define ASM_V   (ASM_K + LPAD * 128)            // 32768 + 14336 = 47104
#define ASM_TOT (ASM_V + 64 * 240)              // 47104 + 15360 = 62464

__device__ __forceinline__ uint32_t swz128(int row, int chunk) {
    return (uint32_t)(row * 128 + ((chunk ^ (row & 7)) << 4));
}

__global__ void __launch_bounds__(256, 2) attn_kernel()
{
    extern __shared__ char asmem[];
    const uint32_t sb = smem_to_u32(asmem);
    const uint32_t sQh = sb + ASM_Q,  sQl = sQh + 128 * 128;
    const uint32_t sK  = sb + ASM_K;
    const uint32_t sV  = sb + ASM_V;

    const int tid  = threadIdx.x;
    const int wid  = tid >> 5;
    const int lane = tid & 31;
    const int bh = blockIdx.y;
    const int batch = bh / NHEADS;
    const int h = bh % NHEADS;
    const int qrow0 = batch * S_ + blockIdx.x * 128;

    // ---- loads (one-shot, cp.async) ----
    {
        const __half* qh = g_q_hi + (size_t)qrow0 * H_ + h * DH;
        const __half* ql = g_q_lo + (size_t)qrow0 * H_ + h * DH;
        #pragma unroll
        for (int i = 0; i < 4; i++) {
            int idx = i * 256 + tid;            // 0..1023
            int row = idx >> 3, c = idx & 7;
            CP_ASYNC_16(sQh + swz128(row, c), qh + (size_t)row * H_ + c * 8);
            CP_ASYNC_16(sQl + swz128(row, c), ql + (size_t)row * H_ + c * 8);
        }
        const __half* kp = g_k + (size_t)batch * LPAD * H_ + h * DH;
        for (int idx = tid; idx < LPAD * 8; idx += 256) {
            int row = idx >> 3, c = idx & 7;
            CP_ASYNC_16(sK + swz128(row, c), kp + (size_t)row * H_ + c * 8);
        }
        const __half* vp = g_vt + ((size_t)batch * H_ + h * DH) * LPAD2;
        for (int idx = tid; idx < 64 * 14; idx += 256) {
            int row = idx / 14, c = idx % 14;
            CP_ASYNC_16(sV + (uint32_t)(row * 240 + c * 16),
                        vp + (size_t)row * LPAD2 + c * 8);
        }
        CP_COMMIT();
    }
    CP_WAIT0();
    __syncthreads();

    const int gid = lane >> 2, tig = lane & 3;
    const int a_row_off = (lane & 7) + ((lane >> 3) & 1) * 8;
    const int a_half    = lane >> 4;
    const int b_row_off = (lane & 7) + ((lane >> 4) & 1) * 8;
    const int b_half    = (lane >> 3) & 1;

    // q fragments (held across the l-loop): 4 k-steps x hi/lo
    uint32_t fQh[4][4], fQl[4][4];
    #pragma unroll
    for (int ks = 0; ks < 4; ks++) {
        int row = wid * 16 + a_row_off;
        uint32_t ad = swz128(row, ks * 2 + a_half);
        ldsm_x4(fQh[ks][0], fQh[ks][1], fQh[ks][2], fQh[ks][3], sQh + ad);
        ldsm_x4(fQl[ks][0], fQl[ks][1], fQl[ks][2], fQl[ks][3], sQl + ad);
    }

    float acc[8][4];
    #pragma unroll
    for (int nt = 0; nt < 8; nt++)
        #pragma unroll
        for (int c = 0; c < 4; c++) acc[nt][c] = 0.f;
    float rs0 = 0.f, rs1 = 0.f;
    const float scale = 0.125f;

    #pragma unroll
    for (int kt = 0; kt < 7; kt++) {       // l tiles of 16 (0..111)
        // --- QK scores for n-tiles 2kt, 2kt+1 ---
        float c0[4] = {0.f, 0.f, 0.f, 0.f};
        float c1[4] = {0.f, 0.f, 0.f, 0.f};
        #pragma unroll
        for (int ks = 0; ks < 4; ks++) {
            int row = kt * 16 + b_row_off;
            uint32_t bd = swz128(row, ks * 2 + b_half);
            uint32_t kb0, kb1, kb2, kb3;
            ldsm_x4(kb0, kb1, kb2, kb3, sK + bd);
            mma_f16(c0, fQh[ks], kb0, kb1);
            mma_f16(c1, fQh[ks], kb2, kb3);
            mma_f16(c0, fQl[ks], kb0, kb1);
            mma_f16(c1, fQl[ks], kb2, kb3);
        }
        // --- exp + mask + row sums ---
        float e0[4], e1[4];
        #pragma unroll
        for (int j = 0; j < 4; j++) {
            e0[j] = __expf(c0[j] * scale);
            e1[j] = __expf(c1[j] * scale);
        }
        if (kt == 6) {   // n-tile 13: cols 104..111, mask col >= 109
            float m0v = (104 + 2 * tig <= 108) ? 1.f : 0.f;
            float m1v = (105 + 2 * tig <= 108) ? 1.f : 0.f;
            e1[0] *= m0v; e1[1] *= m1v; e1[2] *= m0v; e1[3] *= m1v;
        }
        rs0 += e0[0] + e0[1] + e1[0] + e1[1];
        rs1 += e0[2] + e0[3] + e1[2] + e1[3];
        // --- p fragments (FA2 C->A repack) + fp16 lo split ---
        uint32_t ah[4], al[4];
        float ev[8] = {e0[0], e0[1], e0[2], e0[3], e1[0], e1[1], e1[2], e1[3]};
        #pragma unroll
        for (int j = 0; j < 4; j++) {
            __half2 hh = __floats2half2_rn(ev[2 * j], ev[2 * j + 1]);
            ah[j] = h2_bits(hh);
            __half2 ll = __floats2half2_rn(ev[2 * j]     - __half2float(hh.x),
                                           ev[2 * j + 1] - __half2float(hh.y));
            al[j] = h2_bits(ll);
        }
        // --- PV: acc += p @ V^T-tile (k16 = these 16 l's) ---
        #pragma unroll
        for (int g = 0; g < 4; g++) {
            uint32_t bd = (uint32_t)((g * 16 + b_row_off) * 240 +
                                     (kt * 2 + b_half) * 16);
            uint32_t vb0, vb1, vb2, vb3;
            ldsm_x4(vb0, vb1, vb2, vb3, sV + bd);
            mma_f16(acc[g * 2 + 0], ah, vb0, vb1);
            mma_f16(acc[g * 2 + 1], ah, vb2, vb3);
            mma_f16(acc[g * 2 + 0], al, vb0, vb1);
            mma_f16(acc[g * 2 + 1], al, vb2, vb3);
        }
    }

    // quad reduction of row sums
    rs0 += __shfl_xor_sync(0xffffffffu, rs0, 1);
    rs0 += __shfl_xor_sync(0xffffffffu, rs0, 2);
    rs1 += __shfl_xor_sync(0xffffffffu, rs1, 1);
    rs1 += __shfl_xor_sync(0xffffffffu, rs1, 2);
    const float inv0 = 1.f / rs0;
    const float inv1 = 1.f / rs1;

    // epilogue: normalize, split, store to g_att_hi/lo
    const int r0 = qrow0 + wid * 16 + gid;
    #pragma unroll
    for (int nt = 0; nt < 8; nt++) {
        int col = h * DH + nt * 8 + tig * 2;
        __half h0, l0, h1, l1;
        f16split(acc[nt][0] * inv0, h0, l0);
        f16split(acc[nt][1] * inv0, h1, l1);
        size_t a = (size_t)r0 * H_ + col;
        *(__half2*)(g_att_hi + a) = __half2(h0, h1);
        *(__half2*)(g_att_lo + a) = __half2(l0, l1);
        f16split(acc[nt][2] * inv1, h0, l0);
        f16split(acc[nt][3] * inv1, h1, l1);
        a = (size_t)(r0 + 8) * H_ + col;
        *(__half2*)(g_att_hi + a) = __half2(h0, h1);
        *(__half2*)(g_att_lo + a) = __half2(l0, l1);
    }
}

// ---------------------------------------------------------------------------
// Side streams + events for fork/join inside graph capture (host objects,
// created once; no device memory involved).
// ---------------------------------------------------------------------------
struct SideStreams {
    cudaStream_t s1, s2;
    cudaEvent_t ef1, ef2, e_kv, e_w;
    SideStreams() {
        cudaStreamCreateWithFlags(&s1, cudaStreamNonBlocking);
        cudaStreamCreateWithFlags(&s2, cudaStreamNonBlocking);
        cudaEventCreateWithFlags(&ef1, cudaEventDisableTiming);
        cudaEventCreateWithFlags(&ef2, cudaEventDisableTiming);
        cudaEventCreateWithFlags(&e_kv, cudaEventDisableTiming);
        cudaEventCreateWithFlags(&e_w, cudaEventDisableTiming);
    }
};
static SideStreams& side() { static SideStreams s; return s; }

// ---------------------------------------------------------------------------
extern "C" void kernel_launch(void* const* d_in, const int* in_sizes, int n_in,
                              void* d_out, int out_size)
{
    (void)in_sizes; (void)n_in; (void)out_size;
    const float* hs    = (const float*)d_in[0];
    const float* ehs   = (const float*)d_in[1];
    const float* idemb = (const float*)d_in[2];
    const float* Wq    = (const float*)d_in[3];
    const float* Wk    = (const float*)d_in[4];
    const float* Wv    = (const float*)d_in[5];
    const float* Wid_k = (const float*)d_in[6];
    const float* Wid_v = (const float*)d_in[7];
    const float* Wout  = (const float*)d_in[8];
    const float* bout  = (const float*)d_in[9];
    float* out = (float*)d_out;

    const int attn_smem = ASM_TOT;            // 62,464 B
    const int gemm_smem = NSTAGE * STAGE_B;   // 98,304 B
    cudaFuncSetAttribute(attn_kernel,
                         cudaFuncAttributeMaxDynamicSharedMemorySize, attn_smem);
    cudaFuncSetAttribute(gemm_hmma<0>,
                         cudaFuncAttributeMaxDynamicSharedMemorySize, gemm_smem);
    cudaFuncSetAttribute(gemm_hmma<1>,
                         cudaFuncAttributeMaxDynamicSharedMemorySize, gemm_smem);

    SideStreams& ss = side();

    // Fork: kv on s1, weight transpose on s2, both concurrent with the
    // critical path (split -> gemm0 on the main stream).
    cudaEventRecord(ss.ef1, 0);
    cudaStreamWaitEvent(ss.s1, ss.ef1, 0);
    cudaEventRecord(ss.ef2, 0);
    cudaStreamWaitEvent(ss.s2, ss.ef2, 0);

    kv_kernel<<<dim3(H_ / 64, (B_ * T_ + 63) / 64, 4), 256, 0, ss.s1>>>(
        ehs, idemb, Wk, Wv, Wid_k, Wid_v);
    cudaEventRecord(ss.e_kv, ss.s1);

    tsplit_kernel<<<dim3(H_ / 32, H_ / 32, 2), dim3(32, 8), 0, ss.s2>>>(Wq, Wout);
    cudaEventRecord(ss.e_w, ss.s2);

    // Main stream: hidden_states split
    split_kernel<<<(ROWS * H_ / 4 + 255) / 256, 256>>>(hs);

    // gemm0 needs g_wq (join s2)
    cudaStreamWaitEvent(0, ss.e_w, 0);
    gemm_hmma<0><<<dim3(GN / 128, ROWS / 128), 256, gemm_smem>>>(nullptr, nullptr);

    // attention needs K/V (join s1)
    cudaStreamWaitEvent(0, ss.e_kv, 0);
    attn_kernel<<<dim3(S_ / 128, B_ * NHEADS), 256, attn_smem>>>();

    // out = att @ Wout + bout
    gemm_hmma<1><<<dim3(GN / 128, ROWS / 128), 256, gemm_smem>>>(bout, out);
}